// round 1
// baseline (speedup 1.0000x reference)
#include <cuda_runtime.h>

#define BB 128
#define CC 2
#define HIDD 150
#define AA 8
#define KK 30
#define G 49
#define HP 51
#define NP (HP*HP)      // 2601
#define GG (G*G)        // 2401

// -------- scratch (device globals; no allocation allowed) --------
__device__ float g_h1[BB*HIDD*GG];   // 184 MB
__device__ float g_h2[BB*HIDD*GG];   // 184 MB
__device__ float g_tr[BB*72*NP];     // 95.8 MB  (trans, softmaxed in place -> sT)
__device__ float g_rw[BB*NP];        // reward
__device__ float g_q [BB*AA*NP];     // q_last

// -------- packed f32x2 helpers (FFMA2: 2x fp32 throughput on sm_103a) --------
__device__ __forceinline__ unsigned long long pk2(float lo, float hi){
    unsigned long long r;
    asm("mov.b64 %0, {%1, %2};" : "=l"(r) : "f"(lo), "f"(hi));
    return r;
}
__device__ __forceinline__ void upk2(unsigned long long v, float& lo, float& hi){
    asm("mov.b64 {%0, %1}, %2;" : "=f"(lo), "=f"(hi) : "l"(v));
}
__device__ __forceinline__ unsigned long long ffma2(unsigned long long a,
                                                    unsigned long long b,
                                                    unsigned long long c){
    unsigned long long d;
    asm("fma.rn.f32x2 %0, %1, %2, %3;" : "=l"(d) : "l"(a), "l"(b), "l"(c));
    return d;
}

// ============================================================================
// conv1: h1 = relu(conv3x3(grid[B,2,49,49], h1_w) + h1_b)  (pad=1)
// grid: (5 cout-groups of 30, 1, B); 256 threads
// ============================================================================
__global__ void conv1_kernel(const float* __restrict__ gin,
                             const float* __restrict__ w,
                             const float* __restrict__ bias){
    __shared__ float gp[CC*HP*HP];     // padded 51x51 per channel, zero border
    __shared__ float ws[30*18];
    __shared__ float bs[30];
    const int b = blockIdx.z, cog = blockIdx.x;
    const int tid = threadIdx.x;

    for(int i=tid;i<CC*HP*HP;i+=blockDim.x) gp[i]=0.f;
    __syncthreads();
    for(int i=tid;i<CC*GG;i+=blockDim.x){
        int c=i/GG, p=i%GG, y=p/G, x=p%G;
        gp[c*NP + (y+1)*HP + (x+1)] = gin[(b*CC+c)*GG + p];
    }
    for(int i=tid;i<30*18;i+=blockDim.x){
        int co=i/18, r=i%18;
        ws[i] = w[(cog*30+co)*18 + r];
    }
    if(tid<30) bs[tid]=bias[cog*30+tid];
    __syncthreads();

    for(int p=tid;p<GG;p+=blockDim.x){
        int y=p/G, x=p%G;
        float xr[18];
        #pragma unroll
        for(int c=0;c<2;c++)
            #pragma unroll
            for(int i=0;i<3;i++)
                #pragma unroll
                for(int j=0;j<3;j++)
                    xr[c*9+i*3+j] = gp[c*NP + (y+i)*HP + (x+j)];
        #pragma unroll 5
        for(int co=0;co<30;co++){
            float acc = bs[co];
            #pragma unroll
            for(int r=0;r<18;r++) acc = fmaf(ws[co*18+r], xr[r], acc);
            g_h1[((b*HIDD + cog*30+co)*G + y)*G + x] = fmaxf(acc, 0.f);
        }
    }
}

// ============================================================================
// conv2: h2 = relu(conv3x3(h1, h2_w) + h2_b)  (pad=1, 150->150)
// Block: 10 output channels x 20 rows x 50 cols, thread = 2x2 pixel quad,
// two vertical pixels packed into one f32x2 lane.  blockDim (25,10)=250.
// grid: (15 cout-groups, 3 row tiles, B)
// ============================================================================
__global__ void conv2_kernel(const float* __restrict__ w,
                             const float* __restrict__ bias){
    __shared__ __align__(16) float in_s[22*52];      // rows r0-1..r0+20, cols -1..49(+pad)
    __shared__ unsigned long long w2s[10*9];
    const int cg = blockIdx.x, r0 = 20*blockIdx.y, b = blockIdx.z;
    const int tx = threadIdx.x, ty = threadIdx.y;
    const int tid = ty*25 + tx;
    const int xo = 2*tx, yo = r0 + 2*ty;

    unsigned long long accL[10], accR[10];
    #pragma unroll
    for(int co=0;co<10;co++){ accL[co]=0ULL; accR[co]=0ULL; }

    const float* inb = g_h1 + (long)b*HIDD*GG;

    for(int cin=0; cin<HIDD; cin++){
        __syncthreads();
        const float* inc = inb + cin*GG;
        for(int i=tid;i<22*52;i+=250){
            int r=i/52, c=i%52;
            int gr=r0-1+r, gc=c-1;
            float v=0.f;
            if(gr>=0 && gr<G && gc>=0 && gc<G && c<51) v = inc[gr*G+gc];
            in_s[i]=v;
        }
        if(tid<90){
            int co=tid/9, k=tid%9;
            float wv = w[((cg*10+co)*HIDD + cin)*9 + k];
            w2s[tid] = pk2(wv, wv);
        }
        __syncthreads();

        float x[4][4];
        #pragma unroll
        for(int i=0;i<4;i++){
            const float2* rp = (const float2*)&in_s[(2*ty+i)*52 + xo];
            float2 v0 = rp[0], v1 = rp[1];
            x[i][0]=v0.x; x[i][1]=v0.y; x[i][2]=v1.x; x[i][3]=v1.y;
        }
        unsigned long long P[3][4];
        #pragma unroll
        for(int i=0;i<3;i++)
            #pragma unroll
            for(int j=0;j<4;j++) P[i][j]=pk2(x[i][j], x[i+1][j]);

        #pragma unroll
        for(int co=0;co<10;co++){
            unsigned long long aL=accL[co], aR=accR[co];
            #pragma unroll
            for(int i=0;i<3;i++){
                #pragma unroll
                for(int j=0;j<3;j++){
                    unsigned long long wv = w2s[co*9 + i*3 + j];
                    aL = ffma2(wv, P[i][j],   aL);
                    aR = ffma2(wv, P[i][j+1], aR);
                }
            }
            accL[co]=aL; accR[co]=aR;
        }
    }

    #pragma unroll
    for(int co=0;co<10;co++){
        int cout = cg*10+co;
        float bv = bias[cout];
        float o00,o10,o01,o11;
        upk2(accL[co], o00, o10);
        upk2(accR[co], o01, o11);
        o00=fmaxf(o00+bv,0.f); o10=fmaxf(o10+bv,0.f);
        o01=fmaxf(o01+bv,0.f); o11=fmaxf(o11+bv,0.f);
        float* op = g_h2 + ((long)b*HIDD+cout)*GG;
        if(yo<G){
            if(xo  <G) op[yo*G+xo  ]=o00;
            if(xo+1<G) op[yo*G+xo+1]=o01;
        }
        if(yo+1<G){
            if(xo  <G) op[(yo+1)*G+xo  ]=o10;
            if(xo+1<G) op[(yo+1)*G+xo+1]=o11;
        }
    }
}

// ============================================================================
// trans+reward conv: from h2, pad=2, out 51x51.  Channels 0..71 -> trans (t_w),
// channel 72 -> reward (r_w).  Same 2x2-quad f32x2 structure.
// blockDim (26,10)=260; grid (8 ch-groups, 3 row tiles, B)
// ============================================================================
__global__ void trans_kernel(const float* __restrict__ tw,
                             const float* __restrict__ rww){
    __shared__ __align__(16) float in_s[22*54];      // rows r0-2..r0+19, cols -2..50(+pad)
    __shared__ unsigned long long w2s[10*9];
    const int cg = blockIdx.x, r0 = 20*blockIdx.y, b = blockIdx.z;
    const int tx = threadIdx.x, ty = threadIdx.y;
    const int tid = ty*26 + tx;
    const int xo = 2*tx, yo = r0 + 2*ty;

    unsigned long long accL[10], accR[10];
    #pragma unroll
    for(int co=0;co<10;co++){ accL[co]=0ULL; accR[co]=0ULL; }

    const float* inb = g_h2 + (long)b*HIDD*GG;

    for(int cin=0; cin<HIDD; cin++){
        __syncthreads();
        const float* inc = inb + cin*GG;
        for(int i=tid;i<22*54;i+=260){
            int r=i/54, c=i%54;
            int gr=r0-2+r, gc=c-2;
            float v=0.f;
            if(gr>=0 && gr<G && gc>=0 && gc<G) v = inc[gr*G+gc];
            in_s[i]=v;
        }
        if(tid<90){
            int co=tid/9, k=tid%9;
            int ch = cg*10+co;
            float wv = 0.f;
            if(ch<72)       wv = tw[(ch*HIDD+cin)*9 + k];
            else if(ch==72) wv = rww[cin*9 + k];
            w2s[tid] = pk2(wv, wv);
        }
        __syncthreads();

        float x[4][4];
        #pragma unroll
        for(int i=0;i<4;i++){
            const float2* rp = (const float2*)&in_s[(2*ty+i)*54 + xo];
            float2 v0 = rp[0], v1 = rp[1];
            x[i][0]=v0.x; x[i][1]=v0.y; x[i][2]=v1.x; x[i][3]=v1.y;
        }
        unsigned long long P[3][4];
        #pragma unroll
        for(int i=0;i<3;i++)
            #pragma unroll
            for(int j=0;j<4;j++) P[i][j]=pk2(x[i][j], x[i+1][j]);

        #pragma unroll
        for(int co=0;co<10;co++){
            unsigned long long aL=accL[co], aR=accR[co];
            #pragma unroll
            for(int i=0;i<3;i++){
                #pragma unroll
                for(int j=0;j<3;j++){
                    unsigned long long wv = w2s[co*9 + i*3 + j];
                    aL = ffma2(wv, P[i][j],   aL);
                    aR = ffma2(wv, P[i][j+1], aR);
                }
            }
            accL[co]=aL; accR[co]=aR;
        }
    }

    #pragma unroll
    for(int co=0;co<10;co++){
        int ch = cg*10+co;
        if(ch>=73) continue;
        float o00,o10,o01,o11;
        upk2(accL[co], o00, o10);
        upk2(accR[co], o01, o11);
        float* op = (ch<72) ? (g_tr + ((long)b*72+ch)*NP) : (g_rw + (long)b*NP);
        if(yo<HP){
            if(xo  <HP) op[yo*HP+xo  ]=o00;
            if(xo+1<HP) op[yo*HP+xo+1]=o01;
        }
        if(yo+1<HP){
            if(xo  <HP) op[(yo+1)*HP+xo  ]=o10;
            if(xo+1<HP) op[(yo+1)*HP+xo+1]=o11;
        }
    }
}

// ============================================================================
// softmax over the 9 kernel taps (in place on g_tr)
// ============================================================================
__global__ void softmax_kernel(){
    int idx = blockIdx.x*blockDim.x + threadIdx.x;
    if(idx >= BB*AA*NP) return;
    int p = idx % NP, ba = idx / NP;
    float* base = g_tr + (long)ba*9*NP + p;
    float t[9];
    #pragma unroll
    for(int k=0;k<9;k++) t[k] = base[k*NP];
    float m = t[0];
    #pragma unroll
    for(int k=1;k<9;k++) m = fmaxf(m, t[k]);
    float s = 0.f;
    #pragma unroll
    for(int k=0;k<9;k++){ t[k] = __expf(t[k]-m); s += t[k]; }
    float inv = 1.f/s;
    #pragma unroll
    for(int k=0;k<9;k++) base[k*NP] = t[k]*inv;
}

// ============================================================================
// Value iteration: K=30 steps.  Batches are independent -> block per batch,
// v ping-pong in smem (53x53 zero-padded), sT streamed from L2.
// ============================================================================
__global__ void vi_kernel(){
    __shared__ float vp[2][53*53];
    __shared__ float rw[NP];
    const int b = blockIdx.x, tid = threadIdx.x;
    for(int i=tid;i<2*53*53;i+=blockDim.x) ((float*)vp)[i]=0.f;
    for(int i=tid;i<NP;i+=blockDim.x) rw[i]=g_rw[(long)b*NP + i];
    __syncthreads();

    const float* sTb = g_tr + (long)b*72*NP;
    for(int t=0;t<KK;t++){
        const int cur = t&1, nxt = cur^1;
        const bool last = (t==KK-1);
        for(int p=tid;p<NP;p+=blockDim.x){
            int y=p/HP, x=p%HP;
            float n[9];
            #pragma unroll
            for(int i=0;i<3;i++)
                #pragma unroll
                for(int j=0;j<3;j++)
                    n[i*3+j] = vp[cur][(y+i)*53 + (x+j)];
            float r = rw[p];
            float vmax = -3.4e38f;
            #pragma unroll 2
            for(int a=0;a<AA;a++){
                const float* s = sTb + a*9*NP + p;
                float q0 = fmaf(s[0*NP], n[0], r);
                q0 = fmaf(s[3*NP], n[3], q0);
                q0 = fmaf(s[6*NP], n[6], q0);
                float q1 = s[1*NP]*n[1];
                q1 = fmaf(s[4*NP], n[4], q1);
                q1 = fmaf(s[7*NP], n[7], q1);
                float q2 = s[2*NP]*n[2];
                q2 = fmaf(s[5*NP], n[5], q2);
                q2 = fmaf(s[8*NP], n[8], q2);
                float q = q0+q1+q2;
                if(last) g_q[((long)b*AA+a)*NP + p] = q;
                vmax = fmaxf(vmax, q);
            }
            vp[nxt][(y+1)*53 + (x+1)] = vmax;
        }
        __syncthreads();
    }
}

// ============================================================================
// Head: mid = relu(q_c @ a1_w^T + a1_b); logits = mid @ a2_w^T + a2_b
// ============================================================================
__global__ void head_kernel(const float* __restrict__ a1w,
                            const float* __restrict__ a1b,
                            const float* __restrict__ a2w,
                            const float* __restrict__ a2b,
                            float* __restrict__ out){
    __shared__ float s1w[HIDD*AA], s1b[HIDD], s2w[AA*HIDD], s2b[AA];
    const int b = blockIdx.x, tid = threadIdx.x;
    for(int i=tid;i<HIDD*AA;i+=blockDim.x){ s1w[i]=a1w[i]; s2w[i]=a2w[i]; }
    for(int i=tid;i<HIDD;i+=blockDim.x) s1b[i]=a1b[i];
    if(tid<AA) s2b[tid]=a2b[tid];
    __syncthreads();

    for(int p=tid;p<GG;p+=blockDim.x){
        int y=p/G, x=p%G;
        float q[AA], l[AA];
        #pragma unroll
        for(int a=0;a<AA;a++) q[a] = g_q[((long)b*AA+a)*NP + y*HP + x];
        #pragma unroll
        for(int a=0;a<AA;a++) l[a] = s2b[a];
        for(int c=0;c<HIDD;c++){
            float m = s1b[c];
            #pragma unroll
            for(int a=0;a<AA;a++) m = fmaf(q[a], s1w[c*AA+a], m);
            m = fmaxf(m, 0.f);
            #pragma unroll
            for(int a=0;a<AA;a++) l[a] = fmaf(m, s2w[a*HIDD+c], l[a]);
        }
        #pragma unroll
        for(int a=0;a<AA;a++) out[(((long)b*AA+a)*G+y)*G + x] = l[a];
    }
}

// ============================================================================
extern "C" void kernel_launch(void* const* d_in, const int* in_sizes, int n_in,
                              void* d_out, int out_size){
    const float* gin = (const float*)d_in[0];
    // d_in[1], d_in[2]: x_coord/y_coord (unused by reference)
    const float* h1w = (const float*)d_in[3];
    const float* h1b = (const float*)d_in[4];
    const float* h2w = (const float*)d_in[5];
    const float* h2b = (const float*)d_in[6];
    const float* rww = (const float*)d_in[7];
    const float* tww = (const float*)d_in[8];
    const float* a1w = (const float*)d_in[9];
    const float* a1b = (const float*)d_in[10];
    const float* a2w = (const float*)d_in[11];
    const float* a2b = (const float*)d_in[12];
    float* out = (float*)d_out;

    conv1_kernel<<<dim3(5,1,BB), 256>>>(gin, h1w, h1b);
    conv2_kernel<<<dim3(15,3,BB), dim3(25,10)>>>(h2w, h2b);
    trans_kernel<<<dim3(8,3,BB), dim3(26,10)>>>(tww, rww);
    {
        int n = BB*AA*NP;
        softmax_kernel<<<(n+255)/256, 256>>>();
    }
    vi_kernel<<<BB, 512>>>();
    head_kernel<<<BB, 256>>>(a1w, a1b, a2w, a2b, out);
}

// round 4
// speedup vs baseline: 3.2190x; 3.2190x over previous
#include <cuda_runtime.h>
#include <cuda_bf16.h>
#include <cstdint>

#define BB 128
#define CC 2
#define HIDD 150
#define AA 8
#define KK 30
#define G 49
#define HP 51
#define NP (HP*HP)      // 2601
#define GG (G*G)        // 2401
#define KTOT 1350       // 150*9
#define NCHUNK 22       // ceil(1350/64) -> padded K = 1408

// -------- scratch (device globals; no allocation allowed) --------
__device__ float g_h1[BB*HIDD*GG];
__device__ float g_h2[BB*HIDD*GG];
__device__ float g_tr[BB*72*NP];
__device__ float g_rw[BB*NP];
__device__ float g_q [BB*AA*NP];

// ============================ helpers ============================
__device__ __forceinline__ uint32_t smem_u32(const void* p){
    uint32_t a;
    asm("{ .reg .u64 t; cvta.to.shared.u64 t, %1; cvt.u32.u64 %0, t; }" : "=r"(a) : "l"(p));
    return a;
}
#define SW128(o) ((o) ^ (((o) >> 3) & 0x70))

__device__ __forceinline__ void ldsm4(uint32_t* r, uint32_t a){
    asm volatile("ldmatrix.sync.aligned.m8n8.x4.shared.b16 {%0,%1,%2,%3}, [%4];"
        : "=r"(r[0]), "=r"(r[1]), "=r"(r[2]), "=r"(r[3]) : "r"(a));
}
__device__ __forceinline__ void mma_bf16(float* c, const uint32_t* a, uint32_t b0, uint32_t b1){
    asm volatile("mma.sync.aligned.m16n8k16.row.col.f32.bf16.bf16.f32 "
        "{%0,%1,%2,%3}, {%4,%5,%6,%7}, {%8,%9}, {%0,%1,%2,%3};"
        : "+f"(c[0]), "+f"(c[1]), "+f"(c[2]), "+f"(c[3])
        : "r"(a[0]), "r"(a[1]), "r"(a[2]), "r"(a[3]), "r"(b0), "r"(b1));
}
__device__ __forceinline__ void hilo(float v, unsigned short& h, unsigned short& l){
    __nv_bfloat16 bh = __float2bfloat16(v);
    h = __bfloat16_as_ushort(bh);
    l = __bfloat16_as_ushort(__float2bfloat16(v - __bfloat162float(bh)));
}

// ============================================================================
// conv1 (tiny, scalar): h1 = relu(conv3x3(grid, h1_w) + h1_b)
// ============================================================================
__global__ void conv1_kernel(const float* __restrict__ gin,
                             const float* __restrict__ w,
                             const float* __restrict__ bias){
    __shared__ float gp[CC*HP*HP];
    __shared__ float ws[30*18];
    __shared__ float bs[30];
    const int b = blockIdx.z, cog = blockIdx.x;
    const int tid = threadIdx.x;

    for(int i=tid;i<CC*HP*HP;i+=blockDim.x) gp[i]=0.f;
    __syncthreads();
    for(int i=tid;i<CC*GG;i+=blockDim.x){
        int c=i/GG, p=i%GG, y=p/G, x=p%G;
        gp[c*NP + (y+1)*HP + (x+1)] = gin[(b*CC+c)*GG + p];
    }
    for(int i=tid;i<30*18;i+=blockDim.x) ws[i] = w[(cog*30)*18 + i];
    if(tid<30) bs[tid]=bias[cog*30+tid];
    __syncthreads();

    for(int p=tid;p<GG;p+=blockDim.x){
        int y=p/G, x=p%G;
        float xr[18];
        #pragma unroll
        for(int c=0;c<2;c++)
            #pragma unroll
            for(int i=0;i<3;i++)
                #pragma unroll
                for(int j=0;j<3;j++)
                    xr[c*9+i*3+j] = gp[c*NP + (y+i)*HP + (x+j)];
        #pragma unroll 5
        for(int co=0;co<30;co++){
            float acc = bs[co];
            #pragma unroll
            for(int r=0;r<18;r++) acc = fmaf(ws[co*18+r], xr[r], acc);
            g_h1[((b*HIDD + cog*30+co)*G + y)*G + x] = fmaxf(acc, 0.f);
        }
    }
}

// ============================================================================
// Implicit-GEMM conv via mma.sync bf16 (hi/lo split, 3 passes -> ~fp32 acc).
//   D[pixel, cout] = sum_k A[pixel,k] * W[cout,k], k = cin*9 + 3*dy + dx
// 512 threads = 16 warps (4m x 4n). Block tile: 128 pixels x NPAD couts.
// K chunks of 64, double-buffered smem, software pipelined.
// ============================================================================
template<int NPIX, int OUTW, int NCOUT, int NPAD, int PADOFF, bool ISTRANS>
__global__ void __launch_bounds__(512,1) conv_mma_kernel(
        const float* __restrict__ w,     // [rows, 1350]
        const float* __restrict__ w2,    // reward weights (trans only)
        const float* __restrict__ bias){ // conv2 bias
    extern __shared__ char smc[];
    constexpr int NT8 = NPAD/32;         // n8 tiles per warp (6 or 4)
    constexpr int AOFF = 8192;           // A buffers: 4 x 16KB (buf x hi/lo)
    constexpr int BOFF = AOFF + 4*16384; // 73728
    constexpr int BSZ  = NPAD*128;

    const int tid = threadIdx.x;
    const int wid = tid>>5, lane = tid&31;
    const int warp_m = wid & 3, warp_n = wid >> 2;
    const int pbase = blockIdx.x * 128;
    const int b = blockIdx.y;
    const uint32_t smb = smem_u32(smc);
    uint32_t* kt = (uint32_t*)smc;              // [1408]
    float* sbias = (float*)(smc + 5632);

    for(int k = tid; k < NCHUNK*64; k += 512){
        int cin = k/9, rem = k - cin*9;
        kt[k] = (cin<HIDD) ? ((uint32_t)(cin<<8)|((rem/3)<<4)|(rem%3)) : 0xFFFFFFFFu;
    }
    if(!ISTRANS) for(int i=tid;i<NCOUT;i+=512) sbias[i]=bias[i];
    __syncthreads();

    const int r = tid & 127, q = tid >> 7;
    const int p = pbase + r;
    const bool pvr = (p < NPIX);
    const int y = p/OUTW, x = p - y*OUTW;
    const float* inb = (ISTRANS ? g_h2 : g_h1) + (long)b*HIDD*GG;

    float acc[2][NT8][4];
    #pragma unroll
    for(int mt=0;mt<2;mt++)
        #pragma unroll
        for(int nt=0;nt<NT8;nt++)
            #pragma unroll
            for(int i=0;i<4;i++) acc[mt][nt][i]=0.f;

    auto fill = [&](int ch, int buf){
        // ---- A (im2col): thread fills row r, k = q*16 .. q*16+15 ----
        char* Ah = smc + AOFF + (buf*2+0)*16384;
        char* Al = smc + AOFF + (buf*2+1)*16384;
        #pragma unroll
        for(int j=0;j<8;j++){
            int kl = q*16 + j*2;
            int kg = ch*64 + kl;
            uint32_t e0 = kt[kg], e1 = kt[kg+1];
            float v0=0.f, v1=0.f;
            if(pvr && e0!=0xFFFFFFFFu){
                int cin=e0>>8, dy=(e0>>4)&15, dx=e0&15;
                int yy=y+dy-PADOFF, xx=x+dx-PADOFF;
                if(yy>=0&&yy<G&&xx>=0&&xx<G) v0=__ldg(&inb[cin*GG+yy*G+xx]);
            }
            if(pvr && e1!=0xFFFFFFFFu){
                int cin=e1>>8, dy=(e1>>4)&15, dx=e1&15;
                int yy=y+dy-PADOFF, xx=x+dx-PADOFF;
                if(yy>=0&&yy<G&&xx>=0&&xx<G) v1=__ldg(&inb[cin*GG+yy*G+xx]);
            }
            unsigned short h0,l0,h1,l1;
            hilo(v0,h0,l0); hilo(v1,h1,l1);
            uint32_t off = SW128((uint32_t)(r*128 + kl*2));
            *(uint32_t*)(Ah+off) = (uint32_t)h0 | ((uint32_t)h1<<16);
            *(uint32_t*)(Al+off) = (uint32_t)l0 | ((uint32_t)l1<<16);
        }
        // ---- B (weights) ----
        char* Bh = smc + BOFF + (buf*2+0)*BSZ;
        char* Bl = Bh + BSZ;
        #pragma unroll
        for(int it=0; it<NPAD/16; it++){
            int idx = it*512 + tid;
            int row = idx>>5, pp = idx&31;
            int kg = ch*64 + pp*2;
            float v0=0.f, v1=0.f;
            if(kg < KTOT){
                const float* src = nullptr;
                if(!ISTRANS){ if(row<NCOUT) src = w + (long)row*KTOT; }
                else { if(row<72) src = w + (long)row*KTOT; else if(row==72) src = w2; }
                if(src){ v0 = __ldg(src+kg); v1 = __ldg(src+kg+1); }
            }
            unsigned short h0,l0,h1,l1;
            hilo(v0,h0,l0); hilo(v1,h1,l1);
            uint32_t off = SW128((uint32_t)(row*128 + pp*4));
            *(uint32_t*)(Bh+off) = (uint32_t)h0 | ((uint32_t)h1<<16);
            *(uint32_t*)(Bl+off) = (uint32_t)l0 | ((uint32_t)l1<<16);
        }
    };

    auto domma = [&](int buf){
        uint32_t Ahb = smb + AOFF + (buf*2)*16384;
        uint32_t Alb = Ahb + 16384;
        uint32_t Bhb = smb + BOFF + (buf*2)*BSZ;
        uint32_t Blb = Bhb + BSZ;
        const int lrow = lane & 15, lkb = (lane>>4)*16;
        #pragma unroll
        for(int ks=0; ks<4; ks++){
            uint32_t ah[2][4], al[2][4];
            #pragma unroll
            for(int mt=0; mt<2; mt++){
                uint32_t off = SW128((uint32_t)((warp_m*32 + mt*16 + lrow)*128 + ks*32 + lkb));
                ldsm4(ah[mt], Ahb + off);
                ldsm4(al[mt], Alb + off);
            }
            #pragma unroll
            for(int np=0; np<NT8/2; np++){
                uint32_t off = SW128((uint32_t)((warp_n*(NT8*8) + np*16 + lrow)*128 + ks*32 + lkb));
                uint32_t bh[4], bl[4];
                ldsm4(bh, Bhb + off);
                ldsm4(bl, Blb + off);
                // ldmatrix x4 over n16xk16: r0=(n0-7,k0-7) r1=(n8-15,k0-7)
                //                           r2=(n0-7,k8-15) r3=(n8-15,k8-15)
                // B frag for n-tile0 = {r0,r2}; n-tile1 = {r1,r3}.
                #pragma unroll
                for(int mt=0; mt<2; mt++){
                    mma_bf16(acc[mt][2*np],   ah[mt], bh[0], bh[2]);
                    mma_bf16(acc[mt][2*np+1], ah[mt], bh[1], bh[3]);
                    mma_bf16(acc[mt][2*np],   al[mt], bh[0], bh[2]);
                    mma_bf16(acc[mt][2*np+1], al[mt], bh[1], bh[3]);
                    mma_bf16(acc[mt][2*np],   ah[mt], bl[0], bl[2]);
                    mma_bf16(acc[mt][2*np+1], ah[mt], bl[1], bl[3]);
                }
            }
        }
    };

    fill(0, 0);
    __syncthreads();
    for(int ch=0; ch<NCHUNK; ch++){
        if(ch+1 < NCHUNK) fill(ch+1, (ch+1)&1);
        domma(ch&1);
        __syncthreads();
    }

    // ---- epilogue: c frag (row=lane>>2 [+8], col=(lane&3)*2 [+1]) ----
    #pragma unroll
    for(int mt=0; mt<2; mt++){
        int p0 = pbase + warp_m*32 + mt*16 + (lane>>2);
        #pragma unroll
        for(int nt=0; nt<NT8; nt++){
            int co = warp_n*(NT8*8) + nt*8 + (lane&3)*2;
            float* c = acc[mt][nt];
            #pragma unroll
            for(int i=0;i<4;i++){
                int pe = p0 + (i>>1)*8;
                int ce = co + (i&1);
                if(pe >= NPIX) continue;
                float v = c[i];
                if(!ISTRANS){
                    if(ce < NCOUT){
                        v = fmaxf(v + sbias[ce], 0.f);
                        g_h2[((long)b*HIDD + ce)*GG + pe] = v;
                    }
                } else {
                    if(ce < 72)       g_tr[((long)b*72 + ce)*NP + pe] = v;
                    else if(ce == 72) g_rw[(long)b*NP + pe] = v;
                }
            }
        }
    }
}

// ============================================================================
// softmax over the 9 kernel taps (in place on g_tr)
// ============================================================================
__global__ void softmax_kernel(){
    int idx = blockIdx.x*blockDim.x + threadIdx.x;
    if(idx >= BB*AA*NP) return;
    int p = idx % NP, ba = idx / NP;
    float* base = g_tr + (long)ba*9*NP + p;
    float t[9];
    #pragma unroll
    for(int k=0;k<9;k++) t[k] = base[k*NP];
    float m = t[0];
    #pragma unroll
    for(int k=1;k<9;k++) m = fmaxf(m, t[k]);
    float s = 0.f;
    #pragma unroll
    for(int k=0;k<9;k++){ t[k] = __expf(t[k]-m); s += t[k]; }
    float inv = 1.f/s;
    #pragma unroll
    for(int k=0;k<9;k++) base[k*NP] = t[k]*inv;
}

// ============================================================================
// Value iteration: K=30 steps, block per batch, v ping-pong in smem
// ============================================================================
__global__ void vi_kernel(){
    __shared__ float vp[2][53*53];
    __shared__ float rw[NP];
    const int b = blockIdx.x, tid = threadIdx.x;
    for(int i=tid;i<2*53*53;i+=blockDim.x) ((float*)vp)[i]=0.f;
    for(int i=tid;i<NP;i+=blockDim.x) rw[i]=g_rw[(long)b*NP + i];
    __syncthreads();

    const float* sTb = g_tr + (long)b*72*NP;
    for(int t=0;t<KK;t++){
        const int cur = t&1, nxt = cur^1;
        const bool last = (t==KK-1);
        for(int p=tid;p<NP;p+=blockDim.x){
            int y=p/HP, x=p%HP;
            float n[9];
            #pragma unroll
            for(int i=0;i<3;i++)
                #pragma unroll
                for(int j=0;j<3;j++)
                    n[i*3+j] = vp[cur][(y+i)*53 + (x+j)];
            float r = rw[p];
            float vmax = -3.4e38f;
            #pragma unroll 2
            for(int a=0;a<AA;a++){
                const float* s = sTb + a*9*NP + p;
                float q0 = fmaf(s[0*NP], n[0], r);
                q0 = fmaf(s[3*NP], n[3], q0);
                q0 = fmaf(s[6*NP], n[6], q0);
                float q1 = s[1*NP]*n[1];
                q1 = fmaf(s[4*NP], n[4], q1);
                q1 = fmaf(s[7*NP], n[7], q1);
                float q2 = s[2*NP]*n[2];
                q2 = fmaf(s[5*NP], n[5], q2);
                q2 = fmaf(s[8*NP], n[8], q2);
                float q = q0+q1+q2;
                if(last) g_q[((long)b*AA+a)*NP + p] = q;
                vmax = fmaxf(vmax, q);
            }
            vp[nxt][(y+1)*53 + (x+1)] = vmax;
        }
        __syncthreads();
    }
}

// ============================================================================
// Head: mid = relu(q_c @ a1_w^T + a1_b); logits = mid @ a2_w^T + a2_b
// ============================================================================
__global__ void head_kernel(const float* __restrict__ a1w,
                            const float* __restrict__ a1b,
                            const float* __restrict__ a2w,
                            const float* __restrict__ a2b,
                            float* __restrict__ out){
    __shared__ float s1w[HIDD*AA], s1b[HIDD], s2w[AA*HIDD], s2b[AA];
    const int b = blockIdx.x, tid = threadIdx.x;
    for(int i=tid;i<HIDD*AA;i+=blockDim.x){ s1w[i]=a1w[i]; s2w[i]=a2w[i]; }
    for(int i=tid;i<HIDD;i+=blockDim.x) s1b[i]=a1b[i];
    if(tid<AA) s2b[tid]=a2b[tid];
    __syncthreads();

    for(int p=tid;p<GG;p+=blockDim.x){
        int y=p/G, x=p%G;
        float q[AA], l[AA];
        #pragma unroll
        for(int a=0;a<AA;a++) q[a] = g_q[((long)b*AA+a)*NP + y*HP + x];
        #pragma unroll
        for(int a=0;a<AA;a++) l[a] = s2b[a];
        for(int c=0;c<HIDD;c++){
            float m = s1b[c];
            #pragma unroll
            for(int a=0;a<AA;a++) m = fmaf(q[a], s1w[c*AA+a], m);
            m = fmaxf(m, 0.f);
            #pragma unroll
            for(int a=0;a<AA;a++) l[a] = fmaf(m, s2w[a*HIDD+c], l[a]);
        }
        #pragma unroll
        for(int a=0;a<AA;a++) out[(((long)b*AA+a)*G+y)*G + x] = l[a];
    }
}

__global__ void dummy_kernel(){}

// ============================================================================
extern "C" void kernel_launch(void* const* d_in, const int* in_sizes, int n_in,
                              void* d_out, int out_size){
    const float* gin = (const float*)d_in[0];
    const float* h1w = (const float*)d_in[3];
    const float* h1b = (const float*)d_in[4];
    const float* h2w = (const float*)d_in[5];
    const float* h2b = (const float*)d_in[6];
    const float* rww = (const float*)d_in[7];
    const float* tww = (const float*)d_in[8];
    const float* a1w = (const float*)d_in[9];
    const float* a1b = (const float*)d_in[10];
    const float* a2w = (const float*)d_in[11];
    const float* a2b = (const float*)d_in[12];
    float* out = (float*)d_out;

    auto conv2_k = conv_mma_kernel<GG, G, HIDD, 192, 1, false>;
    auto trans_k = conv_mma_kernel<NP, HP, 73, 128, 2, true>;
    const int conv2_smem = 73728 + 4*192*128;   // 172032
    const int trans_smem = 73728 + 4*128*128;   // 139264
    cudaFuncSetAttribute(conv2_k, cudaFuncAttributeMaxDynamicSharedMemorySize, conv2_smem);
    cudaFuncSetAttribute(trans_k, cudaFuncAttributeMaxDynamicSharedMemorySize, trans_smem);

    conv1_kernel<<<dim3(5,1,BB), 256>>>(gin, h1w, h1b);
    dummy_kernel<<<1, 32>>>();
    dummy_kernel<<<1, 32>>>();
    conv2_k<<<dim3(19, BB), 512, conv2_smem>>>(h2w, nullptr, h2b);   // ncu window target
    trans_k<<<dim3(21, BB), 512, trans_smem>>>(tww, rww, nullptr);
    {
        int n = BB*AA*NP;
        softmax_kernel<<<(n+255)/256, 256>>>();
    }
    vi_kernel<<<BB, 512>>>();
    head_kernel<<<BB, 256>>>(a1w, a1b, a2w, a2b, out);
}

// round 5
// speedup vs baseline: 3.5011x; 1.0876x over previous
#include <cuda_runtime.h>
#include <cuda_bf16.h>
#include <cstdint>

#define BB 128
#define CC 2
#define HIDD 150
#define AA 8
#define KK 30
#define G 49
#define HP 51
#define NP (HP*HP)      // 2601
#define GG (G*G)        // 2401
#define CINP 160        // padded cin (10 chunks of 16)
#define NCH 10

// padded image sizes
#define P1W 51
#define P1N (51*51)     // 2601 (h1 padded by 1)
#define P2W 53
#define P2N (53*53)     // 2809 (h2 padded by 2)

// -------- scratch (device globals; .bss zero-init, halos/pads stay zero) ----
__device__ __align__(16) __nv_bfloat16 g_h1h[(long)BB*P1N*CINP];
__device__ __align__(16) __nv_bfloat16 g_h1l[(long)BB*P1N*CINP];
__device__ __align__(16) __nv_bfloat16 g_h2h[(long)BB*P2N*CINP];
__device__ __align__(16) __nv_bfloat16 g_h2l[(long)BB*P2N*CINP];
__device__ __align__(16) __nv_bfloat16 g_w2h[9*NCH*192*24];
__device__ __align__(16) __nv_bfloat16 g_w2l[9*NCH*192*24];
__device__ __align__(16) __nv_bfloat16 g_wth[9*NCH*128*24];
__device__ __align__(16) __nv_bfloat16 g_wtl[9*NCH*128*24];
__device__ float g_tr[(long)BB*72*NP];
__device__ float g_rw[BB*NP];
__device__ float g_q [(long)BB*AA*NP];

// ============================ helpers ============================
__device__ __forceinline__ uint32_t smem_u32(const void* p){
    uint32_t a;
    asm("{ .reg .u64 t; cvta.to.shared.u64 t, %1; cvt.u32.u64 %0, t; }" : "=r"(a) : "l"(p));
    return a;
}
__device__ __forceinline__ void ldsm4(uint32_t* r, uint32_t a){
    asm volatile("ldmatrix.sync.aligned.m8n8.x4.shared.b16 {%0,%1,%2,%3}, [%4];"
        : "=r"(r[0]), "=r"(r[1]), "=r"(r[2]), "=r"(r[3]) : "r"(a));
}
__device__ __forceinline__ void mma_bf16(float* c, const uint32_t* a, uint32_t b0, uint32_t b1){
    asm volatile("mma.sync.aligned.m16n8k16.row.col.f32.bf16.bf16.f32 "
        "{%0,%1,%2,%3}, {%4,%5,%6,%7}, {%8,%9}, {%0,%1,%2,%3};"
        : "+f"(c[0]), "+f"(c[1]), "+f"(c[2]), "+f"(c[3])
        : "r"(a[0]), "r"(a[1]), "r"(a[2]), "r"(a[3]), "r"(b0), "r"(b1));
}
__device__ __forceinline__ void hilo(float v, unsigned short& h, unsigned short& l){
    __nv_bfloat16 bh = __float2bfloat16(v);
    h = __bfloat16_as_ushort(bh);
    l = __bfloat16_as_ushort(__float2bfloat16(v - __bfloat162float(bh)));
}

// ============================================================================
// weight prep: reorganize conv2/trans/reward weights into ldsm-ready hi/lo
// tiles: [tap][chunk][cout rows][24 cols bf16] (16 cols used, 48B row stride)
// ============================================================================
__global__ void prep_w_kernel(const float* __restrict__ h2w,
                              const float* __restrict__ tw,
                              const float* __restrict__ rww){
    const int N2 = 9*NCH*192*16;
    const int NT = 9*NCH*128*16;
    int idx = blockIdx.x*blockDim.x + threadIdx.x;
    if(idx < N2){
        int ci = idx & 15; int r = idx >> 4;
        int co = r % 192; r /= 192;
        int c = r % NCH;  int t = r / NCH;
        int cin = c*16 + ci;
        float v = 0.f;
        if(co < 150 && cin < 150) v = h2w[(co*150 + cin)*9 + t];
        unsigned short h,l; hilo(v,h,l);
        long o = ((long)(t*NCH+c)*192 + co)*24 + ci;
        g_w2h[o] = __ushort_as_bfloat16(h);
        g_w2l[o] = __ushort_as_bfloat16(l);
    } else if(idx < N2+NT){
        int j = idx - N2;
        int ci = j & 15; int r = j >> 4;
        int co = r % 128; r /= 128;
        int c = r % NCH;  int t = r / NCH;
        int cin = c*16 + ci;
        float v = 0.f;
        if(cin < 150){
            if(co < 72)       v = tw[(co*150 + cin)*9 + t];
            else if(co == 72) v = rww[cin*9 + t];
        }
        unsigned short h,l; hilo(v,h,l);
        long o = ((long)(t*NCH+c)*128 + co)*24 + ci;
        g_wth[o] = __ushort_as_bfloat16(h);
        g_wtl[o] = __ushort_as_bfloat16(l);
    }
}

// ============================================================================
// conv1 (tiny, scalar): h1 = relu(conv3x3(grid) + b), store padded bf16 hi/lo
// ============================================================================
__global__ void conv1_kernel(const float* __restrict__ gin,
                             const float* __restrict__ w,
                             const float* __restrict__ bias){
    __shared__ float gp[CC*HP*HP];
    __shared__ float ws[30*18];
    __shared__ float bs[30];
    const int b = blockIdx.z, cog = blockIdx.x;
    const int tid = threadIdx.x;

    for(int i=tid;i<CC*HP*HP;i+=blockDim.x) gp[i]=0.f;
    __syncthreads();
    for(int i=tid;i<CC*GG;i+=blockDim.x){
        int c=i/GG, p=i%GG, y=p/G, x=p%G;
        gp[c*NP + (y+1)*HP + (x+1)] = gin[(b*CC+c)*GG + p];
    }
    for(int i=tid;i<30*18;i+=blockDim.x) ws[i] = w[(cog*30)*18 + i];
    if(tid<30) bs[tid]=bias[cog*30+tid];
    __syncthreads();

    const long xb = (long)b*P1N*CINP;
    for(int p=tid;p<GG;p+=blockDim.x){
        int y=p/G, x=p%G;
        float xr[18];
        #pragma unroll
        for(int c=0;c<2;c++)
            #pragma unroll
            for(int i=0;i<3;i++)
                #pragma unroll
                for(int j=0;j<3;j++)
                    xr[c*9+i*3+j] = gp[c*NP + (y+i)*HP + (x+j)];
        long pb = xb + (long)((y+1)*P1W + (x+1))*CINP + cog*30;
        #pragma unroll 5
        for(int co=0;co<30;co++){
            float acc = bs[co];
            #pragma unroll
            for(int r=0;r<18;r++) acc = fmaf(ws[co*18+r], xr[r], acc);
            acc = fmaxf(acc, 0.f);
            unsigned short h,l; hilo(acc,h,l);
            g_h1h[pb+co] = __ushort_as_bfloat16(h);
            g_h1l[pb+co] = __ushort_as_bfloat16(l);
        }
    }
}

// ============================================================================
// Shifted-GEMM conv via mma.sync bf16 (hi/lo, 3 passes).
// conv = sum over 9 taps: X_shift[px, cin] @ W_tap[cin, cout].
// A tile = raw padded input (one load per cin-chunk, shared by all taps);
// tap shift handled by per-lane ldmatrix row addresses (offset dy*WPAD+dx).
// 512 thr = 16 warps (4m x 4n), 128-pixel tile, cin chunks of 16.
// ============================================================================
template<int OUTW, int NPIX, int WPAD, int PADPIX, int NPAD, bool ISTRANS>
__global__ void __launch_bounds__(512,1) conv_shift_kernel(
        const __nv_bfloat16* __restrict__ Xh, const __nv_bfloat16* __restrict__ Xl,
        const __nv_bfloat16* __restrict__ Wh, const __nv_bfloat16* __restrict__ Wl,
        const float* __restrict__ bias,
        __nv_bfloat16* __restrict__ Yh, __nv_bfloat16* __restrict__ Yl){
    constexpr int NT8  = NPAD/32;
    constexpr int TILEB = NPAD*48;
    constexpr int NB16 = TILEB/16;
    constexpr int ASZ  = 256*48;          // 12288 per plane
    constexpr int BOFF = 4*ASZ;           // after 2buf x 2planes of A
    constexpr int BGRP = 3*2*TILEB;       // 3 taps x hi/lo per buffer
    extern __shared__ __align__(16) char smc[];
    __shared__ float sbias[192];

    const int tid = threadIdx.x, lane = tid & 31, wid = tid >> 5;
    const int warp_m = wid & 3, warp_n = wid >> 2;
    const int pbase = blockIdx.x*128, b = blockIdx.y;
    const uint32_t smb = smem_u32(smc);

    if(!ISTRANS){ for(int i=tid;i<192;i+=512) sbias[i] = (i<150)? bias[i] : 0.f; }

    const int y0 = pbase/OUTW;
    const int ipmin = y0*WPAD + (pbase - y0*OUTW);

    // per-lane A row byte-offsets (tap 0) for the two 16-row m-tiles
    uint32_t arow[2];
    #pragma unroll
    for(int mt=0;mt<2;mt++){
        int pix = pbase + warp_m*32 + mt*16 + (lane&15);
        int row = 0;
        if(pix < NPIX){ int yy = pix/OUTW; row = yy*WPAD + (pix - yy*OUTW) - ipmin; }
        arow[mt] = (uint32_t)(row*48) + (uint32_t)((lane>>4)*16);
    }

    const long xb = (long)b*PADPIX*CINP;

    auto fillA = [&](int c, int buf){
        int rr = tid>>1, half = tid&1;
        int P = ipmin + rr;
        uint4 vh = make_uint4(0,0,0,0), vl = make_uint4(0,0,0,0);
        if(P < PADPIX){
            long so = xb + (long)P*CINP + c*16 + half*8;
            vh = *(const uint4*)(Xh + so);
            vl = *(const uint4*)(Xl + so);
        }
        uint32_t doff = (uint32_t)(rr*48 + half*16);
        *(uint4*)(smc + buf*2*ASZ + doff) = vh;
        *(uint4*)(smc + buf*2*ASZ + ASZ + doff) = vl;
    };

    auto fillB = [&](int cg, int buf){
        int c = cg/3, t0 = (cg - c*3)*3;
        #pragma unroll 2
        for(int idx = tid; idx < 3*2*NB16; idx += 512){
            int tl = idx/(2*NB16);
            int rem = idx - tl*2*NB16;
            int pl = rem/NB16, o = rem - pl*NB16;
            const __nv_bfloat16* src = (pl ? Wl : Wh) + (long)((t0+tl)*NCH + c)*(NPAD*24) + o*8;
            uint4 v = *(const uint4*)src;
            *(uint4*)(smc + BOFF + buf*BGRP + (tl*2+pl)*TILEB + o*16) = v;
        }
    };

    float acc[2][NT8][4];
    #pragma unroll
    for(int mt=0;mt<2;mt++)
        #pragma unroll
        for(int nt=0;nt<NT8;nt++)
            #pragma unroll
            for(int i=0;i<4;i++) acc[mt][nt][i]=0.f;

    auto domma = [&](int g, int abuf, int bbuf){
        uint32_t Ah = smb + abuf*2*ASZ;
        uint32_t Al = Ah + ASZ;
        #pragma unroll
        for(int tl=0; tl<3; tl++){
            int t = g*3 + tl;
            int dy = t/3, dx = t - dy*3;
            uint32_t toff = (uint32_t)((dy*WPAD + dx)*48);
            uint32_t ah[2][4], al[2][4];
            #pragma unroll
            for(int mt=0;mt<2;mt++){
                ldsm4(ah[mt], Ah + arow[mt] + toff);
                ldsm4(al[mt], Al + arow[mt] + toff);
            }
            uint32_t Bh = smb + BOFF + bbuf*BGRP + tl*2*TILEB;
            uint32_t Bl = Bh + TILEB;
            #pragma unroll
            for(int np=0; np<NT8/2; np++){
                uint32_t boff = (uint32_t)((warp_n*(NT8*8) + np*16 + (lane&15))*48 + (lane>>4)*16);
                uint32_t bh[4], bl[4];
                ldsm4(bh, Bh + boff);
                ldsm4(bl, Bl + boff);
                // b-frag: n-tile0 = {r0,r2}, n-tile1 = {r1,r3}
                #pragma unroll
                for(int mt=0;mt<2;mt++){
                    mma_bf16(acc[mt][2*np],   ah[mt], bh[0], bh[2]);
                    mma_bf16(acc[mt][2*np+1], ah[mt], bh[1], bh[3]);
                    mma_bf16(acc[mt][2*np],   al[mt], bh[0], bh[2]);
                    mma_bf16(acc[mt][2*np+1], al[mt], bh[1], bh[3]);
                    mma_bf16(acc[mt][2*np],   ah[mt], bl[0], bl[2]);
                    mma_bf16(acc[mt][2*np+1], ah[mt], bl[1], bl[3]);
                }
            }
        }
    };

    fillA(0, 0);
    fillB(0, 0);
    __syncthreads();
    for(int cg=0; cg<3*NCH; cg++){
        int c = cg/3, g = cg - c*3;
        if(cg < 3*NCH-1) fillB(cg+1, (cg+1)&1);
        if(g == 2 && c < NCH-1) fillA(c+1, (c+1)&1);
        domma(g, c&1, cg&1);
        __syncthreads();
    }

    // ---- epilogue ----
    const long yb2 = (long)b*P2N*CINP;
    #pragma unroll
    for(int mt=0; mt<2; mt++){
        int p0 = pbase + warp_m*32 + mt*16 + (lane>>2);
        #pragma unroll
        for(int nt=0; nt<NT8; nt++){
            int co0 = warp_n*(NT8*8) + nt*8 + (lane&3)*2;
            #pragma unroll
            for(int h=0; h<2; h++){
                int pe = p0 + h*8;
                if(pe >= NPIX) continue;
                float v0 = acc[mt][nt][h*2+0];
                float v1 = acc[mt][nt][h*2+1];
                if(!ISTRANS){
                    if(co0 < 150){
                        v0 = fmaxf(v0 + sbias[co0],   0.f);
                        v1 = fmaxf(v1 + sbias[co0+1], 0.f);
                        unsigned short h0,l0,h1,l1;
                        hilo(v0,h0,l0); hilo(v1,h1,l1);
                        int yy = pe/OUTW, xx = pe - yy*OUTW;
                        long pp = yb2 + (long)((yy+2)*P2W + (xx+2))*CINP + co0;
                        *(uint32_t*)(Yh+pp) = (uint32_t)h0 | ((uint32_t)h1<<16);
                        *(uint32_t*)(Yl+pp) = (uint32_t)l0 | ((uint32_t)l1<<16);
                    }
                } else {
                    #pragma unroll
                    for(int u=0; u<2; u++){
                        int ch = co0 + u;
                        float v = u ? v1 : v0;
                        if(ch < 72)       g_tr[((long)b*72 + ch)*NP + pe] = v;
                        else if(ch == 72) g_rw[(long)b*NP + pe] = v;
                    }
                }
            }
        }
    }
}

// ============================================================================
// softmax over the 9 kernel taps (in place on g_tr)
// ============================================================================
__global__ void softmax_kernel(){
    int idx = blockIdx.x*blockDim.x + threadIdx.x;
    if(idx >= BB*AA*NP) return;
    int p = idx % NP, ba = idx / NP;
    float* base = g_tr + (long)ba*9*NP + p;
    float t[9];
    #pragma unroll
    for(int k=0;k<9;k++) t[k] = base[k*NP];
    float m = t[0];
    #pragma unroll
    for(int k=1;k<9;k++) m = fmaxf(m, t[k]);
    float s = 0.f;
    #pragma unroll
    for(int k=0;k<9;k++){ t[k] = __expf(t[k]-m); s += t[k]; }
    float inv = 1.f/s;
    #pragma unroll
    for(int k=0;k<9;k++) base[k*NP] = t[k]*inv;
}

// ============================================================================
// Value iteration: K=30 steps, block per batch, v ping-pong in smem
// ============================================================================
__global__ void vi_kernel(){
    __shared__ float vp[2][53*53];
    __shared__ float rw[NP];
    const int b = blockIdx.x, tid = threadIdx.x;
    for(int i=tid;i<2*53*53;i+=blockDim.x) ((float*)vp)[i]=0.f;
    for(int i=tid;i<NP;i+=blockDim.x) rw[i]=g_rw[(long)b*NP + i];
    __syncthreads();

    const float* sTb = g_tr + (long)b*72*NP;
    for(int t=0;t<KK;t++){
        const int cur = t&1, nxt = cur^1;
        const bool last = (t==KK-1);
        for(int p=tid;p<NP;p+=blockDim.x){
            int y=p/HP, x=p%HP;
            float n[9];
            #pragma unroll
            for(int i=0;i<3;i++)
                #pragma unroll
                for(int j=0;j<3;j++)
                    n[i*3+j] = vp[cur][(y+i)*53 + (x+j)];
            float r = rw[p];
            float vmax = -3.4e38f;
            #pragma unroll 2
            for(int a=0;a<AA;a++){
                const float* s = sTb + a*9*NP + p;
                float q0 = fmaf(s[0*NP], n[0], r);
                q0 = fmaf(s[3*NP], n[3], q0);
                q0 = fmaf(s[6*NP], n[6], q0);
                float q1 = s[1*NP]*n[1];
                q1 = fmaf(s[4*NP], n[4], q1);
                q1 = fmaf(s[7*NP], n[7], q1);
                float q2 = s[2*NP]*n[2];
                q2 = fmaf(s[5*NP], n[5], q2);
                q2 = fmaf(s[8*NP], n[8], q2);
                float q = q0+q1+q2;
                if(last) g_q[((long)b*AA+a)*NP + p] = q;
                vmax = fmaxf(vmax, q);
            }
            vp[nxt][(y+1)*53 + (x+1)] = vmax;
        }
        __syncthreads();
    }
}

// ============================================================================
// Head
// ============================================================================
__global__ void head_kernel(const float* __restrict__ a1w,
                            const float* __restrict__ a1b,
                            const float* __restrict__ a2w,
                            const float* __restrict__ a2b,
                            float* __restrict__ out){
    __shared__ float s1w[HIDD*AA], s1b[HIDD], s2w[AA*HIDD], s2b[AA];
    const int b = blockIdx.x, tid = threadIdx.x;
    for(int i=tid;i<HIDD*AA;i+=blockDim.x){ s1w[i]=a1w[i]; s2w[i]=a2w[i]; }
    for(int i=tid;i<HIDD;i+=blockDim.x) s1b[i]=a1b[i];
    if(tid<AA) s2b[tid]=a2b[tid];
    __syncthreads();

    for(int p=tid;p<GG;p+=blockDim.x){
        int y=p/G, x=p%G;
        float q[AA], l[AA];
        #pragma unroll
        for(int a=0;a<AA;a++) q[a] = g_q[((long)b*AA+a)*NP + y*HP + x];
        #pragma unroll
        for(int a=0;a<AA;a++) l[a] = s2b[a];
        for(int c=0;c<HIDD;c++){
            float m = s1b[c];
            #pragma unroll
            for(int a=0;a<AA;a++) m = fmaf(q[a], s1w[c*AA+a], m);
            m = fmaxf(m, 0.f);
            #pragma unroll
            for(int a=0;a<AA;a++) l[a] = fmaf(m, s2w[a*HIDD+c], l[a]);
        }
        #pragma unroll
        for(int a=0;a<AA;a++) out[(((long)b*AA+a)*G+y)*G + x] = l[a];
    }
}

__global__ void dummy_kernel(){}

// ============================================================================
extern "C" void kernel_launch(void* const* d_in, const int* in_sizes, int n_in,
                              void* d_out, int out_size){
    const float* gin = (const float*)d_in[0];
    const float* h1w = (const float*)d_in[3];
    const float* h1b = (const float*)d_in[4];
    const float* h2w = (const float*)d_in[5];
    const float* h2b = (const float*)d_in[6];
    const float* rww = (const float*)d_in[7];
    const float* tww = (const float*)d_in[8];
    const float* a1w = (const float*)d_in[9];
    const float* a1b = (const float*)d_in[10];
    const float* a2w = (const float*)d_in[11];
    const float* a2b = (const float*)d_in[12];
    float* out = (float*)d_out;

    __nv_bfloat16 *h1h, *h1l, *h2h, *h2l, *w2h, *w2l, *wth, *wtl;
    cudaGetSymbolAddress((void**)&h1h, g_h1h);
    cudaGetSymbolAddress((void**)&h1l, g_h1l);
    cudaGetSymbolAddress((void**)&h2h, g_h2h);
    cudaGetSymbolAddress((void**)&h2l, g_h2l);
    cudaGetSymbolAddress((void**)&w2h, g_w2h);
    cudaGetSymbolAddress((void**)&w2l, g_w2l);
    cudaGetSymbolAddress((void**)&wth, g_wth);
    cudaGetSymbolAddress((void**)&wtl, g_wtl);

    auto conv2_k = conv_shift_kernel<G, GG, P1W, P1N, 192, false>;
    auto trans_k = conv_shift_kernel<HP, NP, P2W, P2N, 128, true>;
    const int ASZ = 256*48;
    const int conv2_smem = 4*ASZ + 2*(3*2*192*48);  // 49152 + 110592 = 159744
    const int trans_smem = 4*ASZ + 2*(3*2*128*48);  // 49152 + 73728  = 122880
    cudaFuncSetAttribute(conv2_k, cudaFuncAttributeMaxDynamicSharedMemorySize, conv2_smem);
    cudaFuncSetAttribute(trans_k, cudaFuncAttributeMaxDynamicSharedMemorySize, trans_smem);

    {
        int n = 9*NCH*192*16 + 9*NCH*128*16;
        prep_w_kernel<<<(n+255)/256, 256>>>(h2w, tww, rww);
    }
    conv1_kernel<<<dim3(5,1,BB), 256>>>(gin, h1w, h1b);
    dummy_kernel<<<1, 32>>>();
    conv2_k<<<dim3(19, BB), 512, conv2_smem>>>(h1h, h1l, w2h, w2l, h2b, h2h, h2l);
    trans_k<<<dim3(21, BB), 512, trans_smem>>>(h2h, h2l, wth, wtl, nullptr, nullptr, nullptr);
    {
        int n = BB*AA*NP;
        softmax_kernel<<<(n+255)/256, 256>>>();
    }
    vi_kernel<<<BB, 1024>>>();
    head_kernel<<<BB, 256>>>(a1w, a1b, a2w, a2b, out);
}

// round 7
// speedup vs baseline: 4.1612x; 1.1885x over previous
#include <cuda_runtime.h>
#include <cuda_bf16.h>
#include <cstdint>

#define BB 128
#define CC 2
#define HIDD 150
#define AA 8
#define KK 30
#define G 49
#define HP 51
#define NP (HP*HP)      // 2601
#define GG (G*G)        // 2401
#define CINP 160        // padded cin (10 chunks of 16)
#define NCH 10

// padded image sizes
#define P1W 51
#define P1N (51*51)     // 2601 (h1 padded by 1)
#define P2W 53
#define P2N (53*53)     // 2809 (h2 padded by 2)

// -------- scratch (device globals; .bss zero-init, halos/pads stay zero) ----
__device__ __align__(16) __nv_bfloat16 g_h1h[(long)BB*P1N*CINP];
__device__ __align__(16) __nv_bfloat16 g_h1l[(long)BB*P1N*CINP];
__device__ __align__(16) __nv_bfloat16 g_h2h[(long)BB*P2N*CINP];
__device__ __align__(16) __nv_bfloat16 g_h2l[(long)BB*P2N*CINP];
__device__ __align__(16) __nv_bfloat16 g_w2h[9*NCH*192*24];
__device__ __align__(16) __nv_bfloat16 g_w2l[9*NCH*192*24];
__device__ __align__(16) __nv_bfloat16 g_wth[9*NCH*128*24];
__device__ __align__(16) __nv_bfloat16 g_wtl[9*NCH*128*24];
__device__ float g_tr[(long)BB*72*NP];
__device__ float g_rw[BB*NP];
__device__ float g_q [(long)BB*AA*NP];

// ============================ helpers ============================
__device__ __forceinline__ uint32_t smem_u32(const void* p){
    uint32_t a;
    asm("{ .reg .u64 t; cvta.to.shared.u64 t, %1; cvt.u32.u64 %0, t; }" : "=r"(a) : "l"(p));
    return a;
}
__device__ __forceinline__ void ldsm4(uint32_t* r, uint32_t a){
    asm volatile("ldmatrix.sync.aligned.m8n8.x4.shared.b16 {%0,%1,%2,%3}, [%4];"
        : "=r"(r[0]), "=r"(r[1]), "=r"(r[2]), "=r"(r[3]) : "r"(a));
}
__device__ __forceinline__ void mma_bf16(float* c, const uint32_t* a, uint32_t b0, uint32_t b1){
    asm volatile("mma.sync.aligned.m16n8k16.row.col.f32.bf16.bf16.f32 "
        "{%0,%1,%2,%3}, {%4,%5,%6,%7}, {%8,%9}, {%0,%1,%2,%3};"
        : "+f"(c[0]), "+f"(c[1]), "+f"(c[2]), "+f"(c[3])
        : "r"(a[0]), "r"(a[1]), "r"(a[2]), "r"(a[3]), "r"(b0), "r"(b1));
}
__device__ __forceinline__ void hilo(float v, unsigned short& h, unsigned short& l){
    __nv_bfloat16 bh = __float2bfloat16(v);
    h = __bfloat16_as_ushort(bh);
    l = __bfloat16_as_ushort(__float2bfloat16(v - __bfloat162float(bh)));
}

// ============================================================================
// weight prep: [tap][chunk][cout rows][24 cols bf16] hi/lo (16 used, 48B row)
// ============================================================================
__global__ void prep_w_kernel(const float* __restrict__ h2w,
                              const float* __restrict__ tw,
                              const float* __restrict__ rww){
    const int N2 = 9*NCH*192*16;
    const int NT = 9*NCH*128*16;
    int idx = blockIdx.x*blockDim.x + threadIdx.x;
    if(idx < N2){
        int ci = idx & 15; int r = idx >> 4;
        int co = r % 192; r /= 192;
        int c = r % NCH;  int t = r / NCH;
        int cin = c*16 + ci;
        float v = 0.f;
        if(co < 150 && cin < 150) v = h2w[(co*150 + cin)*9 + t];
        unsigned short h,l; hilo(v,h,l);
        long o = ((long)(t*NCH+c)*192 + co)*24 + ci;
        g_w2h[o] = __ushort_as_bfloat16(h);
        g_w2l[o] = __ushort_as_bfloat16(l);
    } else if(idx < N2+NT){
        int j = idx - N2;
        int ci = j & 15; int r = j >> 4;
        int co = r % 128; r /= 128;
        int c = r % NCH;  int t = r / NCH;
        int cin = c*16 + ci;
        float v = 0.f;
        if(cin < 150){
            if(co < 72)       v = tw[(co*150 + cin)*9 + t];
            else if(co == 72) v = rww[cin*9 + t];
        }
        unsigned short h,l; hilo(v,h,l);
        long o = ((long)(t*NCH+c)*128 + co)*24 + ci;
        g_wth[o] = __ushort_as_bfloat16(h);
        g_wtl[o] = __ushort_as_bfloat16(l);
    }
}

// ============================================================================
// conv1 (tiny, scalar): h1 = relu(conv3x3(grid) + b), store padded bf16 hi/lo
// ============================================================================
__global__ void conv1_kernel(const float* __restrict__ gin,
                             const float* __restrict__ w,
                             const float* __restrict__ bias){
    __shared__ float gp[CC*HP*HP];
    __shared__ float ws[30*18];
    __shared__ float bs[30];
    const int b = blockIdx.z, cog = blockIdx.x;
    const int tid = threadIdx.x;

    for(int i=tid;i<CC*HP*HP;i+=blockDim.x) gp[i]=0.f;
    __syncthreads();
    for(int i=tid;i<CC*GG;i+=blockDim.x){
        int c=i/GG, p=i%GG, y=p/G, x=p%G;
        gp[c*NP + (y+1)*HP + (x+1)] = gin[(b*CC+c)*GG + p];
    }
    for(int i=tid;i<30*18;i+=blockDim.x) ws[i] = w[(cog*30)*18 + i];
    if(tid<30) bs[tid]=bias[cog*30+tid];
    __syncthreads();

    const long xb = (long)b*P1N*CINP;
    for(int p=tid;p<GG;p+=blockDim.x){
        int y=p/G, x=p%G;
        float xr[18];
        #pragma unroll
        for(int c=0;c<2;c++)
            #pragma unroll
            for(int i=0;i<3;i++)
                #pragma unroll
                for(int j=0;j<3;j++)
                    xr[c*9+i*3+j] = gp[c*NP + (y+i)*HP + (x+j)];
        long pb = xb + (long)((y+1)*P1W + (x+1))*CINP + cog*30;
        #pragma unroll 5
        for(int co=0;co<30;co++){
            float acc = bs[co];
            #pragma unroll
            for(int r=0;r<18;r++) acc = fmaf(ws[co*18+r], xr[r], acc);
            acc = fmaxf(acc, 0.f);
            unsigned short h,l; hilo(acc,h,l);
            g_h1h[pb+co] = __ushort_as_bfloat16(h);
            g_h1l[pb+co] = __ushort_as_bfloat16(l);
        }
    }
}

// ============================================================================
// Shifted-GEMM conv via mma.sync bf16 (hi/lo, 3 passes).
// 256 thr = 8 warps (4m x 2n), 128-pixel tile x NPC couts (N sub-tile at
// offset nbase within NROWTOT weight rows). 2 CTAs/SM.
// ============================================================================
template<int OUTW, int NPIX, int WPAD, int PADPIX, int NROWTOT, int NPC, bool ISTRANS>
__global__ void __launch_bounds__(256,2) conv_shift_kernel(
        const __nv_bfloat16* __restrict__ Xh, const __nv_bfloat16* __restrict__ Xl,
        const __nv_bfloat16* __restrict__ Wh, const __nv_bfloat16* __restrict__ Wl,
        const float* __restrict__ bias, int nbase,
        __nv_bfloat16* __restrict__ Yh, __nv_bfloat16* __restrict__ Yl){
    constexpr int NT8  = NPC/16;          // n8 tiles per warp (6 or 4)
    constexpr int TILEB = NPC*48;
    constexpr int NB16 = TILEB/16;
    constexpr int ASZ  = 256*48;          // 12288 per plane
    constexpr int BOFF = 4*ASZ;           // 2buf x 2planes of A
    constexpr int BGRP = 3*2*TILEB;       // 3 taps x hi/lo per buffer
    extern __shared__ __align__(16) char smc[];
    __shared__ float sbias[192];

    const int tid = threadIdx.x, lane = tid & 31, wid = tid >> 5;
    const int warp_m = wid & 3, warp_n = wid >> 2;   // 0..3, 0..1
    const int pbase = blockIdx.x*128, b = blockIdx.y;
    const uint32_t smb = smem_u32(smc);

    if(!ISTRANS){ for(int i=tid;i<192;i+=256) sbias[i] = (i<150)? bias[i] : 0.f; }

    const int y0 = pbase/OUTW;
    const int ipmin = y0*WPAD + (pbase - y0*OUTW);

    uint32_t arow[2];
    #pragma unroll
    for(int mt=0;mt<2;mt++){
        int pix = pbase + warp_m*32 + mt*16 + (lane&15);
        int row = 0;
        if(pix < NPIX){ int yy = pix/OUTW; row = yy*WPAD + (pix - yy*OUTW) - ipmin; }
        arow[mt] = (uint32_t)(row*48) + (uint32_t)((lane>>4)*16);
    }

    const long xb = (long)b*PADPIX*CINP;

    auto fillA = [&](int c, int buf){
        int P = ipmin + tid;
        uint4 vh0 = make_uint4(0,0,0,0), vh1 = vh0, vl0 = vh0, vl1 = vh0;
        if(P < PADPIX){
            long so = xb + (long)P*CINP + c*16;
            vh0 = *(const uint4*)(Xh + so);
            vh1 = *(const uint4*)(Xh + so + 8);
            vl0 = *(const uint4*)(Xl + so);
            vl1 = *(const uint4*)(Xl + so + 8);
        }
        uint32_t doff = (uint32_t)(tid*48);
        char* base = smc + buf*2*ASZ;
        *(uint4*)(base + doff)            = vh0;
        *(uint4*)(base + doff + 16)       = vh1;
        *(uint4*)(base + ASZ + doff)      = vl0;
        *(uint4*)(base + ASZ + doff + 16) = vl1;
    };

    auto fillB = [&](int cg, int buf){
        int c = cg/3, t0 = (cg - c*3)*3;
        #pragma unroll 3
        for(int idx = tid; idx < 3*2*NB16; idx += 256){
            int tl = idx/(2*NB16);
            int rem = idx - tl*2*NB16;
            int pl = rem/NB16, o = rem - pl*NB16;
            const __nv_bfloat16* src = (pl ? Wl : Wh)
                + (long)((t0+tl)*NCH + c)*(NROWTOT*24) + nbase*24 + o*8;
            uint4 v = *(const uint4*)src;
            *(uint4*)(smc + BOFF + buf*BGRP + (tl*2+pl)*TILEB + o*16) = v;
        }
    };

    float acc[2][NT8][4];
    #pragma unroll
    for(int mt=0;mt<2;mt++)
        #pragma unroll
        for(int nt=0;nt<NT8;nt++)
            #pragma unroll
            for(int i=0;i<4;i++) acc[mt][nt][i]=0.f;

    auto domma = [&](int g, int abuf, int bbuf){
        uint32_t Ah = smb + abuf*2*ASZ;
        uint32_t Al = Ah + ASZ;
        #pragma unroll
        for(int tl=0; tl<3; tl++){
            int t = g*3 + tl;
            int dy = t/3, dx = t - dy*3;
            uint32_t toff = (uint32_t)((dy*WPAD + dx)*48);
            uint32_t ah[2][4], al[2][4];
            #pragma unroll
            for(int mt=0;mt<2;mt++){
                ldsm4(ah[mt], Ah + arow[mt] + toff);
                ldsm4(al[mt], Al + arow[mt] + toff);
            }
            uint32_t Bh = smb + BOFF + bbuf*BGRP + tl*2*TILEB;
            uint32_t Bl = Bh + TILEB;
            #pragma unroll
            for(int np=0; np<NT8/2; np++){
                uint32_t boff = (uint32_t)((warp_n*(NT8*8) + np*16 + (lane&15))*48 + (lane>>4)*16);
                uint32_t bh[4], bl[4];
                ldsm4(bh, Bh + boff);
                ldsm4(bl, Bl + boff);
                // b-frag: n-tile0 = {r0,r2}, n-tile1 = {r1,r3}
                #pragma unroll
                for(int mt=0;mt<2;mt++){
                    mma_bf16(acc[mt][2*np],   ah[mt], bh[0], bh[2]);
                    mma_bf16(acc[mt][2*np+1], ah[mt], bh[1], bh[3]);
                    mma_bf16(acc[mt][2*np],   al[mt], bh[0], bh[2]);
                    mma_bf16(acc[mt][2*np+1], al[mt], bh[1], bh[3]);
                    mma_bf16(acc[mt][2*np],   ah[mt], bl[0], bl[2]);
                    mma_bf16(acc[mt][2*np+1], ah[mt], bl[1], bl[3]);
                }
            }
        }
    };

    fillA(0, 0);
    fillB(0, 0);
    __syncthreads();
    for(int cg=0; cg<3*NCH; cg++){
        int c = cg/3, g = cg - c*3;
        if(cg < 3*NCH-1) fillB(cg+1, (cg+1)&1);
        if(g == 2 && c < NCH-1) fillA(c+1, (c+1)&1);
        domma(g, c&1, cg&1);
        __syncthreads();
    }

    // ---- epilogue ----
    const long yb2 = (long)b*P2N*CINP;
    #pragma unroll
    for(int mt=0; mt<2; mt++){
        int p0 = pbase + warp_m*32 + mt*16 + (lane>>2);
        #pragma unroll
        for(int nt=0; nt<NT8; nt++){
            int co0 = nbase + warp_n*(NT8*8) + nt*8 + (lane&3)*2;
            #pragma unroll
            for(int h=0; h<2; h++){
                int pe = p0 + h*8;
                if(pe >= NPIX) continue;
                float v0 = acc[mt][nt][h*2+0];
                float v1 = acc[mt][nt][h*2+1];
                if(!ISTRANS){
                    if(co0 < 150){
                        v0 = fmaxf(v0 + sbias[co0],   0.f);
                        v1 = fmaxf(v1 + sbias[co0+1], 0.f);
                        unsigned short h0,l0,h1,l1;
                        hilo(v0,h0,l0); hilo(v1,h1,l1);
                        int yy = pe/OUTW, xx = pe - yy*OUTW;
                        long pp = yb2 + (long)((yy+2)*P2W + (xx+2))*CINP + co0;
                        *(uint32_t*)(Yh+pp) = (uint32_t)h0 | ((uint32_t)h1<<16);
                        *(uint32_t*)(Yl+pp) = (uint32_t)l0 | ((uint32_t)l1<<16);
                    }
                } else {
                    #pragma unroll
                    for(int u=0; u<2; u++){
                        int ch = co0 + u;
                        float v = u ? v1 : v0;
                        if(ch < 72)       g_tr[((long)b*72 + ch)*NP + pe] = v;
                        else if(ch == 72) g_rw[(long)b*NP + pe] = v;
                    }
                }
            }
        }
    }
}

// ============================================================================
// softmax over the 9 kernel taps (in place on g_tr)
// ============================================================================
__global__ void softmax_kernel(){
    int idx = blockIdx.x*blockDim.x + threadIdx.x;
    if(idx >= BB*AA*NP) return;
    int p = idx % NP, ba = idx / NP;
    float* base = g_tr + (long)ba*9*NP + p;
    float t[9];
    #pragma unroll
    for(int k=0;k<9;k++) t[k] = base[k*NP];
    float m = t[0];
    #pragma unroll
    for(int k=1;k<9;k++) m = fmaxf(m, t[k]);
    float s = 0.f;
    #pragma unroll
    for(int k=0;k<9;k++){ t[k] = __expf(t[k]-m); s += t[k]; }
    float inv = 1.f/s;
    #pragma unroll
    for(int k=0;k<9;k++) base[k*NP] = t[k]*inv;
}

// ============================================================================
// Value iteration: K=30 steps, block per batch, v ping-pong in smem
// ============================================================================
__global__ void vi_kernel(){
    __shared__ float vp[2][53*53];
    __shared__ float rw[NP];
    const int b = blockIdx.x, tid = threadIdx.x;
    for(int i=tid;i<2*53*53;i+=blockDim.x) ((float*)vp)[i]=0.f;
    for(int i=tid;i<NP;i+=blockDim.x) rw[i]=g_rw[(long)b*NP + i];
    __syncthreads();

    const float* sTb = g_tr + (long)b*72*NP;
    for(int t=0;t<KK;t++){
        const int cur = t&1, nxt = cur^1;
        const bool last = (t==KK-1);
        for(int p=tid;p<NP;p+=blockDim.x){
            int y=p/HP, x=p%HP;
            float n[9];
            #pragma unroll
            for(int i=0;i<3;i++)
                #pragma unroll
                for(int j=0;j<3;j++)
                    n[i*3+j] = vp[cur][(y+i)*53 + (x+j)];
            float r = rw[p];
            float vmax = -3.4e38f;
            #pragma unroll 2
            for(int a=0;a<AA;a++){
                const float* s = sTb + a*9*NP + p;
                float q0 = fmaf(s[0*NP], n[0], r);
                q0 = fmaf(s[3*NP], n[3], q0);
                q0 = fmaf(s[6*NP], n[6], q0);
                float q1 = s[1*NP]*n[1];
                q1 = fmaf(s[4*NP], n[4], q1);
                q1 = fmaf(s[7*NP], n[7], q1);
                float q2 = s[2*NP]*n[2];
                q2 = fmaf(s[5*NP], n[5], q2);
                q2 = fmaf(s[8*NP], n[8], q2);
                float q = q0+q1+q2;
                if(last) g_q[((long)b*AA+a)*NP + p] = q;
                vmax = fmaxf(vmax, q);
            }
            vp[nxt][(y+1)*53 + (x+1)] = vmax;
        }
        __syncthreads();
    }
}

// ============================================================================
// Head
// ============================================================================
__global__ void head_kernel(const float* __restrict__ a1w,
                            const float* __restrict__ a1b,
                            const float* __restrict__ a2w,
                            const float* __restrict__ a2b,
                            float* __restrict__ out){
    __shared__ float s1w[HIDD*AA], s1b[HIDD], s2w[AA*HIDD], s2b[AA];
    const int b = blockIdx.x, tid = threadIdx.x;
    for(int i=tid;i<HIDD*AA;i+=blockDim.x){ s1w[i]=a1w[i]; s2w[i]=a2w[i]; }
    for(int i=tid;i<HIDD;i+=blockDim.x) s1b[i]=a1b[i];
    if(tid<AA) s2b[tid]=a2b[tid];
    __syncthreads();

    for(int p=tid;p<GG;p+=blockDim.x){
        int y=p/G, x=p%G;
        float q[AA], l[AA];
        #pragma unroll
        for(int a=0;a<AA;a++) q[a] = g_q[((long)b*AA+a)*NP + y*HP + x];
        #pragma unroll
        for(int a=0;a<AA;a++) l[a] = s2b[a];
        for(int c=0;c<HIDD;c++){
            float m = s1b[c];
            #pragma unroll
            for(int a=0;a<AA;a++) m = fmaf(q[a], s1w[c*AA+a], m);
            m = fmaxf(m, 0.f);
            #pragma unroll
            for(int a=0;a<AA;a++) l[a] = fmaf(m, s2w[a*HIDD+c], l[a]);
        }
        #pragma unroll
        for(int a=0;a<AA;a++) out[(((long)b*AA+a)*G+y)*G + x] = l[a];
    }
}

__global__ void dummy_kernel(){}

// ============================================================================
extern "C" void kernel_launch(void* const* d_in, const int* in_sizes, int n_in,
                              void* d_out, int out_size){
    const float* gin = (const float*)d_in[0];
    const float* h1w = (const float*)d_in[3];
    const float* h1b = (const float*)d_in[4];
    const float* h2w = (const float*)d_in[5];
    const float* h2b = (const float*)d_in[6];
    const float* rww = (const float*)d_in[7];
    const float* tww = (const float*)d_in[8];
    const float* a1w = (const float*)d_in[9];
    const float* a1b = (const float*)d_in[10];
    const float* a2w = (const float*)d_in[11];
    const float* a2b = (const float*)d_in[12];
    float* out = (float*)d_out;

    __nv_bfloat16 *h1h, *h1l, *h2h, *h2l, *w2h, *w2l, *wth, *wtl;
    cudaGetSymbolAddress((void**)&h1h, g_h1h);
    cudaGetSymbolAddress((void**)&h1l, g_h1l);
    cudaGetSymbolAddress((void**)&h2h, g_h2h);
    cudaGetSymbolAddress((void**)&h2l, g_h2l);
    cudaGetSymbolAddress((void**)&w2h, g_w2h);
    cudaGetSymbolAddress((void**)&w2l, g_w2l);
    cudaGetSymbolAddress((void**)&wth, g_wth);
    cudaGetSymbolAddress((void**)&wtl, g_wtl);

    auto conv2a_k = conv_shift_kernel<G, GG, P1W, P1N, 192, 96, false>;
    auto conv2b_k = conv_shift_kernel<G, GG, P1W, P1N, 192, 64, false>;
    auto trans_k  = conv_shift_kernel<HP, NP, P2W, P2N, 128, 96, true>;
    const int ASZ = 256*48;
    const int smem96 = 4*ASZ + 2*(3*2*96*48);   // 49152 + 55296 = 104448
    const int smem64 = 4*ASZ + 2*(3*2*64*48);   // 49152 + 36864 = 86016
    cudaFuncSetAttribute(conv2a_k, cudaFuncAttributeMaxDynamicSharedMemorySize, smem96);
    cudaFuncSetAttribute(conv2b_k, cudaFuncAttributeMaxDynamicSharedMemorySize, smem64);
    cudaFuncSetAttribute(trans_k,  cudaFuncAttributeMaxDynamicSharedMemorySize, smem96);

    {
        int n = 9*NCH*192*16 + 9*NCH*128*16;
        prep_w_kernel<<<(n+255)/256, 256>>>(h2w, tww, rww);
    }
    conv1_kernel<<<dim3(5,1,BB), 256>>>(gin, h1w, h1b);
    dummy_kernel<<<1, 32>>>();
    conv2a_k<<<dim3(19, BB), 256, smem96>>>(h1h, h1l, w2h, w2l, h2b, 0,  h2h, h2l);
    conv2b_k<<<dim3(19, BB), 256, smem64>>>(h1h, h1l, w2h, w2l, h2b, 96, h2h, h2l);
    trans_k <<<dim3(21, BB), 256, smem96>>>(h2h, h2l, wth, wtl, nullptr, 0, nullptr, nullptr);
    {
        int n = BB*AA*NP;
        softmax_kernel<<<(n+255)/256, 256>>>();
    }
    vi_kernel<<<BB, 1024>>>();
    head_kernel<<<BB, 256>>>(a1w, a1b, a2w, a2b, out);
}

// round 8
// speedup vs baseline: 4.6030x; 1.1062x over previous
#include <cuda_runtime.h>
#include <cuda_bf16.h>
#include <cstdint>

#define BB 128
#define CC 2
#define HIDD 150
#define AA 8
#define KK 30
#define G 49
#define HP 51
#define NP (HP*HP)      // 2601
#define GG (G*G)        // 2401
#define CINP 160        // padded cin (10 chunks of 16)
#define NCH 10

// padded image sizes
#define P1W 51
#define P1N (51*51)     // 2601 (h1 padded by 1)
#define P2W 53
#define P2N (53*53)     // 2809 (h2 padded by 2)

// -------- scratch (device globals; .bss zero-init, halos/pads stay zero) ----
__device__ __align__(16) __nv_bfloat16 g_h1h[(long)BB*P1N*CINP];
__device__ __align__(16) __nv_bfloat16 g_h1l[(long)BB*P1N*CINP];
__device__ __align__(16) __nv_bfloat16 g_h2h[(long)BB*P2N*CINP];
__device__ __align__(16) __nv_bfloat16 g_h2l[(long)BB*P2N*CINP];
__device__ __align__(16) __nv_bfloat16 g_w2h[9*NCH*192*24];
__device__ __align__(16) __nv_bfloat16 g_w2l[9*NCH*192*24];
__device__ __align__(16) __nv_bfloat16 g_wth[9*NCH*128*24];
__device__ __align__(16) __nv_bfloat16 g_wtl[9*NCH*128*24];
__device__ float g_tr[(long)BB*72*NP];
__device__ float g_rw[BB*NP];
__device__ float g_q [(long)BB*AA*NP];

// ============================ helpers ============================
__device__ __forceinline__ uint32_t smem_u32(const void* p){
    uint32_t a;
    asm("{ .reg .u64 t; cvta.to.shared.u64 t, %1; cvt.u32.u64 %0, t; }" : "=r"(a) : "l"(p));
    return a;
}
__device__ __forceinline__ void ldsm4(uint32_t* r, uint32_t a){
    asm volatile("ldmatrix.sync.aligned.m8n8.x4.shared.b16 {%0,%1,%2,%3}, [%4];"
        : "=r"(r[0]), "=r"(r[1]), "=r"(r[2]), "=r"(r[3]) : "r"(a));
}
__device__ __forceinline__ void mma_bf16(float* c, const uint32_t* a, uint32_t b0, uint32_t b1){
    asm volatile("mma.sync.aligned.m16n8k16.row.col.f32.bf16.bf16.f32 "
        "{%0,%1,%2,%3}, {%4,%5,%6,%7}, {%8,%9}, {%0,%1,%2,%3};"
        : "+f"(c[0]), "+f"(c[1]), "+f"(c[2]), "+f"(c[3])
        : "r"(a[0]), "r"(a[1]), "r"(a[2]), "r"(a[3]), "r"(b0), "r"(b1));
}
__device__ __forceinline__ void hilo(float v, unsigned short& h, unsigned short& l){
    __nv_bfloat16 bh = __float2bfloat16(v);
    h = __bfloat16_as_ushort(bh);
    l = __bfloat16_as_ushort(__float2bfloat16(v - __bfloat162float(bh)));
}
// 16B async copy; src_sz=0 -> zero-fill destination
__device__ __forceinline__ void cpa16(uint32_t s, const void* g, bool valid){
    int sz = valid ? 16 : 0;
    asm volatile("cp.async.cg.shared.global [%0], [%1], 16, %2;"
        :: "r"(s), "l"(g), "r"(sz) : "memory");
}
#define CPA_COMMIT() asm volatile("cp.async.commit_group;" ::: "memory")
#define CPA_WAIT0()  asm volatile("cp.async.wait_group 0;" ::: "memory")

// ============================================================================
// weight prep: [tap][chunk][cout rows][24 cols bf16] hi/lo (16 used, 48B row)
// ============================================================================
__global__ void prep_w_kernel(const float* __restrict__ h2w,
                              const float* __restrict__ tw,
                              const float* __restrict__ rww){
    const int N2 = 9*NCH*192*16;
    const int NT = 9*NCH*128*16;
    int idx = blockIdx.x*blockDim.x + threadIdx.x;
    if(idx < N2){
        int ci = idx & 15; int r = idx >> 4;
        int co = r % 192; r /= 192;
        int c = r % NCH;  int t = r / NCH;
        int cin = c*16 + ci;
        float v = 0.f;
        if(co < 150 && cin < 150) v = h2w[(co*150 + cin)*9 + t];
        unsigned short h,l; hilo(v,h,l);
        long o = ((long)(t*NCH+c)*192 + co)*24 + ci;
        g_w2h[o] = __ushort_as_bfloat16(h);
        g_w2l[o] = __ushort_as_bfloat16(l);
    } else if(idx < N2+NT){
        int j = idx - N2;
        int ci = j & 15; int r = j >> 4;
        int co = r % 128; r /= 128;
        int c = r % NCH;  int t = r / NCH;
        int cin = c*16 + ci;
        float v = 0.f;
        if(cin < 150){
            if(co < 72)       v = tw[(co*150 + cin)*9 + t];
            else if(co == 72) v = rww[cin*9 + t];
        }
        unsigned short h,l; hilo(v,h,l);
        long o = ((long)(t*NCH+c)*128 + co)*24 + ci;
        g_wth[o] = __ushort_as_bfloat16(h);
        g_wtl[o] = __ushort_as_bfloat16(l);
    }
}

// ============================================================================
// conv1 (tiny, scalar): h1 = relu(conv3x3(grid) + b), store padded bf16 hi/lo
// ============================================================================
__global__ void conv1_kernel(const float* __restrict__ gin,
                             const float* __restrict__ w,
                             const float* __restrict__ bias){
    __shared__ float gp[CC*HP*HP];
    __shared__ float ws[30*18];
    __shared__ float bs[30];
    const int b = blockIdx.z, cog = blockIdx.x;
    const int tid = threadIdx.x;

    for(int i=tid;i<CC*HP*HP;i+=blockDim.x) gp[i]=0.f;
    __syncthreads();
    for(int i=tid;i<CC*GG;i+=blockDim.x){
        int c=i/GG, p=i%GG, y=p/G, x=p%G;
        gp[c*NP + (y+1)*HP + (x+1)] = gin[(b*CC+c)*GG + p];
    }
    for(int i=tid;i<30*18;i+=blockDim.x) ws[i] = w[(cog*30)*18 + i];
    if(tid<30) bs[tid]=bias[cog*30+tid];
    __syncthreads();

    const long xb = (long)b*P1N*CINP;
    for(int p=tid;p<GG;p+=blockDim.x){
        int y=p/G, x=p%G;
        float xr[18];
        #pragma unroll
        for(int c=0;c<2;c++)
            #pragma unroll
            for(int i=0;i<3;i++)
                #pragma unroll
                for(int j=0;j<3;j++)
                    xr[c*9+i*3+j] = gp[c*NP + (y+i)*HP + (x+j)];
        long pb = xb + (long)((y+1)*P1W + (x+1))*CINP + cog*30;
        #pragma unroll 5
        for(int co=0;co<30;co++){
            float acc = bs[co];
            #pragma unroll
            for(int r=0;r<18;r++) acc = fmaf(ws[co*18+r], xr[r], acc);
            acc = fmaxf(acc, 0.f);
            unsigned short h,l; hilo(acc,h,l);
            g_h1h[pb+co] = __ushort_as_bfloat16(h);
            g_h1l[pb+co] = __ushort_as_bfloat16(l);
        }
    }
}

// ============================================================================
// Shifted-GEMM conv via mma.sync bf16 (hi/lo, 3 passes), cp.async fills.
// 256 thr = 8 warps (4m x 2n), 128-pixel tile x NPC couts. 2 CTAs/SM.
// ============================================================================
template<int OUTW, int NPIX, int WPAD, int PADPIX, int NROWTOT, int NPC, bool ISTRANS>
__global__ void __launch_bounds__(256,2) conv_shift_kernel(
        const __nv_bfloat16* __restrict__ Xh, const __nv_bfloat16* __restrict__ Xl,
        const __nv_bfloat16* __restrict__ Wh, const __nv_bfloat16* __restrict__ Wl,
        const float* __restrict__ bias, int nbase,
        __nv_bfloat16* __restrict__ Yh, __nv_bfloat16* __restrict__ Yl){
    constexpr int NT8  = NPC/16;          // n8 tiles per warp (6 or 4)
    constexpr int TILEB = NPC*48;
    constexpr int NB16 = TILEB/16;
    constexpr int ASZ  = 256*48;          // 12288 per plane
    constexpr int BOFF = 4*ASZ;           // 2buf x 2planes of A
    constexpr int BGRP = 3*2*TILEB;       // 3 taps x hi/lo per buffer
    extern __shared__ __align__(16) char smc[];
    __shared__ float sbias[192];

    const int tid = threadIdx.x, lane = tid & 31, wid = tid >> 5;
    const int warp_m = wid & 3, warp_n = wid >> 2;   // 0..3, 0..1
    const int pbase = blockIdx.x*128, b = blockIdx.y;
    const uint32_t smb = smem_u32(smc);

    if(!ISTRANS){ for(int i=tid;i<192;i+=256) sbias[i] = (i<150)? bias[i] : 0.f; }

    const int y0 = pbase/OUTW;
    const int ipmin = y0*WPAD + (pbase - y0*OUTW);

    uint32_t arow[2];
    #pragma unroll
    for(int mt=0;mt<2;mt++){
        int pix = pbase + warp_m*32 + mt*16 + (lane&15);
        int row = 0;
        if(pix < NPIX){ int yy = pix/OUTW; row = yy*WPAD + (pix - yy*OUTW) - ipmin; }
        arow[mt] = (uint32_t)(row*48) + (uint32_t)((lane>>4)*16);
    }

    const long xb = (long)b*PADPIX*CINP;

    auto fillA = [&](int c, int buf){
        int P = ipmin + tid;
        bool v = (P < PADPIX);
        long so = xb + (long)P*CINP + c*16;
        uint32_t d = smb + buf*2*ASZ + (uint32_t)(tid*48);
        cpa16(d,            Xh + so,     v);
        cpa16(d + 16,       Xh + so + 8, v);
        cpa16(d + ASZ,      Xl + so,     v);
        cpa16(d + ASZ + 16, Xl + so + 8, v);
    };

    auto fillB = [&](int cg, int buf){
        int c = cg/3, t0 = (cg - c*3)*3;
        #pragma unroll 3
        for(int idx = tid; idx < 3*2*NB16; idx += 256){
            int tl = idx/(2*NB16);
            int rem = idx - tl*2*NB16;
            int pl = rem/NB16, o = rem - pl*NB16;
            const __nv_bfloat16* src = (pl ? Wl : Wh)
                + (long)((t0+tl)*NCH + c)*(NROWTOT*24) + nbase*24 + o*8;
            cpa16(smb + BOFF + buf*BGRP + (uint32_t)((tl*2+pl)*TILEB + o*16), src, true);
        }
    };

    float acc[2][NT8][4];
    #pragma unroll
    for(int mt=0;mt<2;mt++)
        #pragma unroll
        for(int nt=0;nt<NT8;nt++)
            #pragma unroll
            for(int i=0;i<4;i++) acc[mt][nt][i]=0.f;

    auto domma = [&](int g, int abuf, int bbuf){
        uint32_t Ah = smb + abuf*2*ASZ;
        uint32_t Al = Ah + ASZ;
        #pragma unroll
        for(int tl=0; tl<3; tl++){
            int t = g*3 + tl;
            int dy = t/3, dx = t - dy*3;
            uint32_t toff = (uint32_t)((dy*WPAD + dx)*48);
            uint32_t ah[2][4], al[2][4];
            #pragma unroll
            for(int mt=0;mt<2;mt++){
                ldsm4(ah[mt], Ah + arow[mt] + toff);
                ldsm4(al[mt], Al + arow[mt] + toff);
            }
            uint32_t Bh = smb + BOFF + bbuf*BGRP + tl*2*TILEB;
            uint32_t Bl = Bh + TILEB;
            #pragma unroll
            for(int np=0; np<NT8/2; np++){
                uint32_t boff = (uint32_t)((warp_n*(NT8*8) + np*16 + (lane&15))*48 + (lane>>4)*16);
                uint32_t bh[4], bl[4];
                ldsm4(bh, Bh + boff);
                ldsm4(bl, Bl + boff);
                // b-frag: n-tile0 = {r0,r2}, n-tile1 = {r1,r3}
                #pragma unroll
                for(int mt=0;mt<2;mt++){
                    mma_bf16(acc[mt][2*np],   ah[mt], bh[0], bh[2]);
                    mma_bf16(acc[mt][2*np+1], ah[mt], bh[1], bh[3]);
                    mma_bf16(acc[mt][2*np],   al[mt], bh[0], bh[2]);
                    mma_bf16(acc[mt][2*np+1], al[mt], bh[1], bh[3]);
                    mma_bf16(acc[mt][2*np],   ah[mt], bl[0], bl[2]);
                    mma_bf16(acc[mt][2*np+1], ah[mt], bl[1], bl[3]);
                }
            }
        }
    };

    fillA(0, 0);
    fillB(0, 0);
    CPA_COMMIT();
    CPA_WAIT0();
    __syncthreads();
    for(int cg=0; cg<3*NCH; cg++){
        int c = cg/3, g = cg - c*3;
        if(cg < 3*NCH-1) fillB(cg+1, (cg+1)&1);
        if(g == 2 && c < NCH-1) fillA(c+1, (c+1)&1);
        CPA_COMMIT();
        domma(g, c&1, cg&1);
        CPA_WAIT0();
        __syncthreads();
    }

    // ---- epilogue ----
    const long yb2 = (long)b*P2N*CINP;
    #pragma unroll
    for(int mt=0; mt<2; mt++){
        int p0 = pbase + warp_m*32 + mt*16 + (lane>>2);
        #pragma unroll
        for(int nt=0; nt<NT8; nt++){
            int co0 = nbase + warp_n*(NT8*8) + nt*8 + (lane&3)*2;
            #pragma unroll
            for(int h=0; h<2; h++){
                int pe = p0 + h*8;
                if(pe >= NPIX) continue;
                float v0 = acc[mt][nt][h*2+0];
                float v1 = acc[mt][nt][h*2+1];
                if(!ISTRANS){
                    if(co0 < 150){
                        v0 = fmaxf(v0 + sbias[co0],   0.f);
                        v1 = fmaxf(v1 + sbias[co0+1], 0.f);
                        unsigned short h0,l0,h1,l1;
                        hilo(v0,h0,l0); hilo(v1,h1,l1);
                        int yy = pe/OUTW, xx = pe - yy*OUTW;
                        long pp = yb2 + (long)((yy+2)*P2W + (xx+2))*CINP + co0;
                        *(uint32_t*)(Yh+pp) = (uint32_t)h0 | ((uint32_t)h1<<16);
                        *(uint32_t*)(Yl+pp) = (uint32_t)l0 | ((uint32_t)l1<<16);
                    }
                } else {
                    #pragma unroll
                    for(int u=0; u<2; u++){
                        int ch = co0 + u;
                        float v = u ? v1 : v0;
                        if(ch < 72)       g_tr[((long)b*72 + ch)*NP + pe] = v;
                        else if(ch == 72) g_rw[(long)b*NP + pe] = v;
                    }
                }
            }
        }
    }
}

// ============================================================================
// softmax over the 9 kernel taps (in place on g_tr)
// ============================================================================
__global__ void softmax_kernel(){
    int idx = blockIdx.x*blockDim.x + threadIdx.x;
    if(idx >= BB*AA*NP) return;
    int p = idx % NP, ba = idx / NP;
    float* base = g_tr + (long)ba*9*NP + p;
    float t[9];
    #pragma unroll
    for(int k=0;k<9;k++) t[k] = base[k*NP];
    float m = t[0];
    #pragma unroll
    for(int k=1;k<9;k++) m = fmaxf(m, t[k]);
    float s = 0.f;
    #pragma unroll
    for(int k=0;k<9;k++){ t[k] = __expf(t[k]-m); s += t[k]; }
    float inv = 1.f/s;
    #pragma unroll
    for(int k=0;k<9;k++) base[k*NP] = t[k]*inv;
}

// ============================================================================
// Value iteration: K=30 steps, block per batch, v ping-pong in smem
// ============================================================================
__global__ void vi_kernel(){
    __shared__ float vp[2][53*53];
    __shared__ float rw[NP];
    const int b = blockIdx.x, tid = threadIdx.x;
    for(int i=tid;i<2*53*53;i+=blockDim.x) ((float*)vp)[i]=0.f;
    for(int i=tid;i<NP;i+=blockDim.x) rw[i]=g_rw[(long)b*NP + i];
    __syncthreads();

    const float* sTb = g_tr + (long)b*72*NP;
    for(int t=0;t<KK;t++){
        const int cur = t&1, nxt = cur^1;
        const bool last = (t==KK-1);
        for(int p=tid;p<NP;p+=blockDim.x){
            int y=p/HP, x=p%HP;
            float n[9];
            #pragma unroll
            for(int i=0;i<3;i++)
                #pragma unroll
                for(int j=0;j<3;j++)
                    n[i*3+j] = vp[cur][(y+i)*53 + (x+j)];
            float r = rw[p];
            float vmax = -3.4e38f;
            #pragma unroll 2
            for(int a=0;a<AA;a++){
                const float* s = sTb + a*9*NP + p;
                float q0 = fmaf(s[0*NP], n[0], r);
                q0 = fmaf(s[3*NP], n[3], q0);
                q0 = fmaf(s[6*NP], n[6], q0);
                float q1 = s[1*NP]*n[1];
                q1 = fmaf(s[4*NP], n[4], q1);
                q1 = fmaf(s[7*NP], n[7], q1);
                float q2 = s[2*NP]*n[2];
                q2 = fmaf(s[5*NP], n[5], q2);
                q2 = fmaf(s[8*NP], n[8], q2);
                float q = q0+q1+q2;
                if(last) g_q[((long)b*AA+a)*NP + p] = q;
                vmax = fmaxf(vmax, q);
            }
            vp[nxt][(y+1)*53 + (x+1)] = vmax;
        }
        __syncthreads();
    }
}

// ============================================================================
// Head
// ============================================================================
__global__ void head_kernel(const float* __restrict__ a1w,
                            const float* __restrict__ a1b,
                            const float* __restrict__ a2w,
                            const float* __restrict__ a2b,
                            float* __restrict__ out){
    __shared__ float s1w[HIDD*AA], s1b[HIDD], s2w[AA*HIDD], s2b[AA];
    const int b = blockIdx.x, tid = threadIdx.x;
    for(int i=tid;i<HIDD*AA;i+=blockDim.x){ s1w[i]=a1w[i]; s2w[i]=a2w[i]; }
    for(int i=tid;i<HIDD;i+=blockDim.x) s1b[i]=a1b[i];
    if(tid<AA) s2b[tid]=a2b[tid];
    __syncthreads();

    for(int p=tid;p<GG;p+=blockDim.x){
        int y=p/G, x=p%G;
        float q[AA], l[AA];
        #pragma unroll
        for(int a=0;a<AA;a++) q[a] = g_q[((long)b*AA+a)*NP + y*HP + x];
        #pragma unroll
        for(int a=0;a<AA;a++) l[a] = s2b[a];
        for(int c=0;c<HIDD;c++){
            float m = s1b[c];
            #pragma unroll
            for(int a=0;a<AA;a++) m = fmaf(q[a], s1w[c*AA+a], m);
            m = fmaxf(m, 0.f);
            #pragma unroll
            for(int a=0;a<AA;a++) l[a] = fmaf(m, s2w[a*HIDD+c], l[a]);
        }
        #pragma unroll
        for(int a=0;a<AA;a++) out[(((long)b*AA+a)*G+y)*G + x] = l[a];
    }
}

__global__ void dummy_kernel(){}

// ============================================================================
extern "C" void kernel_launch(void* const* d_in, const int* in_sizes, int n_in,
                              void* d_out, int out_size){
    const float* gin = (const float*)d_in[0];
    const float* h1w = (const float*)d_in[3];
    const float* h1b = (const float*)d_in[4];
    const float* h2w = (const float*)d_in[5];
    const float* h2b = (const float*)d_in[6];
    const float* rww = (const float*)d_in[7];
    const float* tww = (const float*)d_in[8];
    const float* a1w = (const float*)d_in[9];
    const float* a1b = (const float*)d_in[10];
    const float* a2w = (const float*)d_in[11];
    const float* a2b = (const float*)d_in[12];
    float* out = (float*)d_out;

    __nv_bfloat16 *h1h, *h1l, *h2h, *h2l, *w2h, *w2l, *wth, *wtl;
    cudaGetSymbolAddress((void**)&h1h, g_h1h);
    cudaGetSymbolAddress((void**)&h1l, g_h1l);
    cudaGetSymbolAddress((void**)&h2h, g_h2h);
    cudaGetSymbolAddress((void**)&h2l, g_h2l);
    cudaGetSymbolAddress((void**)&w2h, g_w2h);
    cudaGetSymbolAddress((void**)&w2l, g_w2l);
    cudaGetSymbolAddress((void**)&wth, g_wth);
    cudaGetSymbolAddress((void**)&wtl, g_wtl);

    auto conv2a_k = conv_shift_kernel<G, GG, P1W, P1N, 192, 96, false>;
    auto conv2b_k = conv_shift_kernel<G, GG, P1W, P1N, 192, 64, false>;
    auto trans_k  = conv_shift_kernel<HP, NP, P2W, P2N, 128, 96, true>;
    const int ASZ = 256*48;
    const int smem96 = 4*ASZ + 2*(3*2*96*48);   // 104448
    const int smem64 = 4*ASZ + 2*(3*2*64*48);   // 86016
    cudaFuncSetAttribute(conv2a_k, cudaFuncAttributeMaxDynamicSharedMemorySize, smem96);
    cudaFuncSetAttribute(conv2b_k, cudaFuncAttributeMaxDynamicSharedMemorySize, smem64);
    cudaFuncSetAttribute(trans_k,  cudaFuncAttributeMaxDynamicSharedMemorySize, smem96);

    {
        int n = 9*NCH*192*16 + 9*NCH*128*16;
        prep_w_kernel<<<(n+255)/256, 256>>>(h2w, tww, rww);
    }
    conv1_kernel<<<dim3(5,1,BB), 256>>>(gin, h1w, h1b);
    dummy_kernel<<<1, 32>>>();
    conv2a_k<<<dim3(19, BB), 256, smem96>>>(h1h, h1l, w2h, w2l, h2b, 0,  h2h, h2l);
    conv2b_k<<<dim3(19, BB), 256, smem64>>>(h1h, h1l, w2h, w2l, h2b, 96, h2h, h2l);
    trans_k <<<dim3(21, BB), 256, smem96>>>(h2h, h2l, wth, wtl, nullptr, 0, nullptr, nullptr);
    {
        int n = BB*AA*NP;
        softmax_kernel<<<(n+255)/256, 256>>>();
    }
    vi_kernel<<<BB, 1024>>>();
    head_kernel<<<BB, 256>>>(a1w, a1b, a2w, a2b, out);
}

// round 9
// speedup vs baseline: 4.9492x; 1.0752x over previous
#include <cuda_runtime.h>
#include <cuda_bf16.h>
#include <cstdint>

#define BB 128
#define CC 2
#define HIDD 150
#define AA 8
#define KK 30
#define G 49
#define HP 51
#define NP (HP*HP)      // 2601
#define GG (G*G)        // 2401
#define CINP 160        // padded cin (10 chunks of 16)
#define NCH 10

// padded image sizes
#define P1W 51
#define P1N (51*51)     // 2601 (h1 padded by 1)
#define P2W 53
#define P2N (53*53)     // 2809 (h2 padded by 2)

// -------- scratch (device globals; .bss zero-init, halos/pads stay zero) ----
__device__ __align__(16) __nv_bfloat16 g_h1h[(long)BB*P1N*CINP];
__device__ __align__(16) __nv_bfloat16 g_h1l[(long)BB*P1N*CINP];
__device__ __align__(16) __nv_bfloat16 g_h2h[(long)BB*P2N*CINP];
__device__ __align__(16) __nv_bfloat16 g_h2l[(long)BB*P2N*CINP];
// weights laid out [chunk][tap][rows][24] so per-chunk-group advance is constant
__device__ __align__(16) __nv_bfloat16 g_w2h[NCH*9*192*24];
__device__ __align__(16) __nv_bfloat16 g_w2l[NCH*9*192*24];
__device__ __align__(16) __nv_bfloat16 g_wth[NCH*9*128*24];
__device__ __align__(16) __nv_bfloat16 g_wtl[NCH*9*128*24];
__device__ float g_tr[(long)BB*72*NP];
__device__ float g_rw[BB*NP];
__device__ float g_q [(long)BB*AA*NP];

// ============================ helpers ============================
__device__ __forceinline__ uint32_t smem_u32(const void* p){
    uint32_t a;
    asm("{ .reg .u64 t; cvta.to.shared.u64 t, %1; cvt.u32.u64 %0, t; }" : "=r"(a) : "l"(p));
    return a;
}
__device__ __forceinline__ void ldsm4(uint32_t* r, uint32_t a){
    asm volatile("ldmatrix.sync.aligned.m8n8.x4.shared.b16 {%0,%1,%2,%3}, [%4];"
        : "=r"(r[0]), "=r"(r[1]), "=r"(r[2]), "=r"(r[3]) : "r"(a));
}
__device__ __forceinline__ void mma_bf16(float* c, const uint32_t* a, uint32_t b0, uint32_t b1){
    asm volatile("mma.sync.aligned.m16n8k16.row.col.f32.bf16.bf16.f32 "
        "{%0,%1,%2,%3}, {%4,%5,%6,%7}, {%8,%9}, {%0,%1,%2,%3};"
        : "+f"(c[0]), "+f"(c[1]), "+f"(c[2]), "+f"(c[3])
        : "r"(a[0]), "r"(a[1]), "r"(a[2]), "r"(a[3]), "r"(b0), "r"(b1));
}
__device__ __forceinline__ void hilo(float v, unsigned short& h, unsigned short& l){
    __nv_bfloat16 bh = __float2bfloat16(v);
    h = __bfloat16_as_ushort(bh);
    l = __bfloat16_as_ushort(__float2bfloat16(v - __bfloat162float(bh)));
}
// 16B async copy; src_sz=0 -> zero-fill destination
__device__ __forceinline__ void cpa16(uint32_t s, const void* g, bool valid){
    int sz = valid ? 16 : 0;
    asm volatile("cp.async.cg.shared.global [%0], [%1], 16, %2;"
        :: "r"(s), "l"(g), "r"(sz) : "memory");
}
#define CPA_COMMIT() asm volatile("cp.async.commit_group;" ::: "memory")
#define CPA_WAIT0()  asm volatile("cp.async.wait_group 0;" ::: "memory")

// ============================================================================
// weight prep: [chunk][tap][cout rows][24 cols bf16] hi/lo (16 used, 48B row)
// ============================================================================
__global__ void prep_w_kernel(const float* __restrict__ h2w,
                              const float* __restrict__ tw,
                              const float* __restrict__ rww){
    const int N2 = 9*NCH*192*16;
    const int NT = 9*NCH*128*16;
    int idx = blockIdx.x*blockDim.x + threadIdx.x;
    if(idx < N2){
        int ci = idx & 15; int r = idx >> 4;
        int co = r % 192; r /= 192;
        int c = r % NCH;  int t = r / NCH;
        int cin = c*16 + ci;
        float v = 0.f;
        if(co < 150 && cin < 150) v = h2w[(co*150 + cin)*9 + t];
        unsigned short h,l; hilo(v,h,l);
        long o = ((long)(c*9 + t)*192 + co)*24 + ci;
        g_w2h[o] = __ushort_as_bfloat16(h);
        g_w2l[o] = __ushort_as_bfloat16(l);
    } else if(idx < N2+NT){
        int j = idx - N2;
        int ci = j & 15; int r = j >> 4;
        int co = r % 128; r /= 128;
        int c = r % NCH;  int t = r / NCH;
        int cin = c*16 + ci;
        float v = 0.f;
        if(cin < 150){
            if(co < 72)       v = tw[(co*150 + cin)*9 + t];
            else if(co == 72) v = rww[cin*9 + t];
        }
        unsigned short h,l; hilo(v,h,l);
        long o = ((long)(c*9 + t)*128 + co)*24 + ci;
        g_wth[o] = __ushort_as_bfloat16(h);
        g_wtl[o] = __ushort_as_bfloat16(l);
    }
}

// ============================================================================
// conv1 (tiny, scalar): h1 = relu(conv3x3(grid) + b), store padded bf16 hi/lo
// ============================================================================
__global__ void conv1_kernel(const float* __restrict__ gin,
                             const float* __restrict__ w,
                             const float* __restrict__ bias){
    __shared__ float gp[CC*HP*HP];
    __shared__ float ws[30*18];
    __shared__ float bs[30];
    const int b = blockIdx.z, cog = blockIdx.x;
    const int tid = threadIdx.x;

    for(int i=tid;i<CC*HP*HP;i+=blockDim.x) gp[i]=0.f;
    __syncthreads();
    for(int i=tid;i<CC*GG;i+=blockDim.x){
        int c=i/GG, p=i%GG, y=p/G, x=p%G;
        gp[c*NP + (y+1)*HP + (x+1)] = gin[(b*CC+c)*GG + p];
    }
    for(int i=tid;i<30*18;i+=blockDim.x) ws[i] = w[(cog*30)*18 + i];
    if(tid<30) bs[tid]=bias[cog*30+tid];
    __syncthreads();

    const long xb = (long)b*P1N*CINP;
    for(int p=tid;p<GG;p+=blockDim.x){
        int y=p/G, x=p%G;
        float xr[18];
        #pragma unroll
        for(int c=0;c<2;c++)
            #pragma unroll
            for(int i=0;i<3;i++)
                #pragma unroll
                for(int j=0;j<3;j++)
                    xr[c*9+i*3+j] = gp[c*NP + (y+i)*HP + (x+j)];
        long pb = xb + (long)((y+1)*P1W + (x+1))*CINP + cog*30;
        #pragma unroll 5
        for(int co=0;co<30;co++){
            float acc = bs[co];
            #pragma unroll
            for(int r=0;r<18;r++) acc = fmaf(ws[co*18+r], xr[r], acc);
            acc = fmaxf(acc, 0.f);
            unsigned short h,l; hilo(acc,h,l);
            g_h1h[pb+co] = __ushort_as_bfloat16(h);
            g_h1l[pb+co] = __ushort_as_bfloat16(l);
        }
    }
}

// ============================================================================
// Shifted-GEMM conv via mma.sync bf16 (hi/lo, 3 passes), cp.async fills.
// 256 thr = 8 warps (4m x 2n), 128-pixel tile x NPC couts. 2 CTAs/SM.
// ISTRANS: fused 9-tap softmax epilogue writing g_tr/g_rw.
// ============================================================================
template<int OUTW, int NPIX, int WPAD, int PADPIX, int NROWTOT, int NPC, bool ISTRANS>
__global__ void __launch_bounds__(256,2) conv_shift_kernel(
        const __nv_bfloat16* __restrict__ Xh, const __nv_bfloat16* __restrict__ Xl,
        const __nv_bfloat16* __restrict__ Wh, const __nv_bfloat16* __restrict__ Wl,
        const float* __restrict__ bias, int nbase,
        __nv_bfloat16* __restrict__ Yh, __nv_bfloat16* __restrict__ Yl){
    constexpr int NT8  = NPC/16;          // n8 tiles per warp (6 or 4)
    constexpr int TILEB = NPC*48;
    constexpr int NB16 = TILEB/16;
    constexpr int ASZ  = 256*48;          // 12288 per plane
    constexpr int BOFF = 4*ASZ;           // 2buf x 2planes of A
    constexpr int BGRP = 3*2*TILEB;       // 3 taps x hi/lo per buffer
    constexpr int BITEMS = 3*2*NB16;
    constexpr int BITERS = (BITEMS + 255)/256;
    extern __shared__ __align__(16) char smc[];
    __shared__ float sbias[192];

    const int tid = threadIdx.x, lane = tid & 31, wid = tid >> 5;
    const int warp_m = wid & 3, warp_n = wid >> 2;   // 0..3, 0..1
    const int pbase = blockIdx.x*128, b = blockIdx.y;
    const uint32_t smb = smem_u32(smc);

    if(!ISTRANS){ for(int i=tid;i<192;i+=256) sbias[i] = (i<150)? bias[i] : 0.f; }

    const int y0 = pbase/OUTW;
    const int ipmin = y0*WPAD + (pbase - y0*OUTW);

    uint32_t arow[2];
    #pragma unroll
    for(int mt=0;mt<2;mt++){
        int pix = pbase + warp_m*32 + mt*16 + (lane&15);
        int row = 0;
        if(pix < NPIX){ int yy = pix/OUTW; row = yy*WPAD + (pix - yy*OUTW) - ipmin; }
        arow[mt] = (uint32_t)(row*48) + (uint32_t)((lane>>4)*16);
    }
    // loop-invariant B fragment offsets
    uint32_t boff[NT8/2];
    #pragma unroll
    for(int np=0;np<NT8/2;np++)
        boff[np] = (uint32_t)((warp_n*(NT8*8) + np*16 + (lane&15))*48 + (lane>>4)*16);

    const long xb = (long)b*PADPIX*CINP;
    // per-thread A src base (advances by 16 per chunk)
    const int PA = ipmin + tid;
    const bool avalid = (PA < PADPIX);
    const long abase = xb + (long)PA*CINP;
    const uint32_t adst = smb + (uint32_t)(tid*48);

    auto fillA = [&](int c, int buf){
        long so = abase + c*16;
        uint32_t d = adst + (uint32_t)(buf*2*ASZ);
        cpa16(d,            Xh + so,     avalid);
        cpa16(d + 16,       Xh + so + 8, avalid);
        cpa16(d + ASZ,      Xl + so,     avalid);
        cpa16(d + ASZ + 16, Xl + so + 8, avalid);
    };

    // W layout: [(c*9 + t)*NROWTOT + row]*24 ; per chunk-group (3 taps) advance
    auto fillB = [&](int cgi, int buf){
        const long base = (long)cgi*(3*NROWTOT*24) + nbase*24;
        #pragma unroll
        for(int it=0; it<BITERS; it++){
            int idx = it*256 + tid;
            if(BITEMS % 256 == 0 || idx < BITEMS){
                int tl = idx/(2*NB16);
                int rem = idx - tl*2*NB16;
                int pl = rem/NB16, o = rem - pl*NB16;
                const __nv_bfloat16* src = (pl ? Wl : Wh) + base + (long)tl*(NROWTOT*24) + o*8;
                cpa16(smb + BOFF + (uint32_t)(buf*BGRP + (tl*2+pl)*TILEB + o*16), src, true);
            }
        }
    };

    float acc[2][NT8][4];
    #pragma unroll
    for(int mt=0;mt<2;mt++)
        #pragma unroll
        for(int nt=0;nt<NT8;nt++)
            #pragma unroll
            for(int i=0;i<4;i++) acc[mt][nt][i]=0.f;

    auto domma = [&](int g, int abuf, int bbuf){
        uint32_t Ah = smb + abuf*2*ASZ;
        uint32_t Al = Ah + ASZ;
        uint32_t Bbase = smb + BOFF + bbuf*BGRP;
        #pragma unroll
        for(int tl=0; tl<3; tl++){
            const int t = g*3 + tl;
            const int dy = t/3, dx = t - dy*3;
            const uint32_t toff = (uint32_t)((dy*WPAD + dx)*48);
            uint32_t ah[2][4], al[2][4];
            #pragma unroll
            for(int mt=0;mt<2;mt++){
                ldsm4(ah[mt], Ah + arow[mt] + toff);
                ldsm4(al[mt], Al + arow[mt] + toff);
            }
            uint32_t Bh = Bbase + tl*2*TILEB;
            uint32_t Bl = Bh + TILEB;
            #pragma unroll
            for(int np=0; np<NT8/2; np++){
                uint32_t bh[4], bl[4];
                ldsm4(bh, Bh + boff[np]);
                ldsm4(bl, Bl + boff[np]);
                // b-frag: n-tile0 = {r0,r2}, n-tile1 = {r1,r3}
                #pragma unroll
                for(int mt=0;mt<2;mt++){
                    mma_bf16(acc[mt][2*np],   ah[mt], bh[0], bh[2]);
                    mma_bf16(acc[mt][2*np+1], ah[mt], bh[1], bh[3]);
                    mma_bf16(acc[mt][2*np],   al[mt], bh[0], bh[2]);
                    mma_bf16(acc[mt][2*np+1], al[mt], bh[1], bh[3]);
                    mma_bf16(acc[mt][2*np],   ah[mt], bl[0], bl[2]);
                    mma_bf16(acc[mt][2*np+1], ah[mt], bl[1], bl[3]);
                }
            }
        }
    };

    fillA(0, 0);
    fillB(0, 0);
    CPA_COMMIT();
    CPA_WAIT0();
    __syncthreads();
    for(int c=0; c<NCH; c++){
        #pragma unroll
        for(int g=0; g<3; g++){
            const int cgi = c*3 + g;
            if(cgi < 3*NCH-1) fillB(cgi+1, (cgi+1)&1);
            if(g == 2 && c < NCH-1) fillA(c+1, (c+1)&1);
            CPA_COMMIT();
            domma(g, c&1, cgi&1);
            CPA_WAIT0();
            __syncthreads();
        }
    }

    if(!ISTRANS){
        // ---- conv2 epilogue: bias+relu, store padded bf16 hi/lo ----
        const long yb2 = (long)b*P2N*CINP;
        #pragma unroll
        for(int mt=0; mt<2; mt++){
            int p0 = pbase + warp_m*32 + mt*16 + (lane>>2);
            #pragma unroll
            for(int nt=0; nt<NT8; nt++){
                int co0 = nbase + warp_n*(NT8*8) + nt*8 + (lane&3)*2;
                #pragma unroll
                for(int h=0; h<2; h++){
                    int pe = p0 + h*8;
                    if(pe >= NPIX) continue;
                    if(co0 < 150){
                        float v0 = fmaxf(acc[mt][nt][h*2+0] + sbias[co0],   0.f);
                        float v1 = fmaxf(acc[mt][nt][h*2+1] + sbias[co0+1], 0.f);
                        unsigned short h0,l0,h1,l1;
                        hilo(v0,h0,l0); hilo(v1,h1,l1);
                        int yy = pe/OUTW, xx = pe - yy*OUTW;
                        long pp = yb2 + (long)((yy+2)*P2W + (xx+2))*CINP + co0;
                        *(uint32_t*)(Yh+pp) = (uint32_t)h0 | ((uint32_t)h1<<16);
                        *(uint32_t*)(Yl+pp) = (uint32_t)l0 | ((uint32_t)l1<<16);
                    }
                }
            }
        }
    } else {
        // ---- trans epilogue: stage all couts in smem, fused 9-tap softmax ----
        float* stage = (float*)smc;   // 128 x 76 floats (38912 B, smem free now)
        #pragma unroll
        for(int mt=0; mt<2; mt++){
            int pl0 = warp_m*32 + mt*16 + (lane>>2);
            #pragma unroll
            for(int nt=0; nt<NT8; nt++){
                int co0 = warp_n*(NT8*8) + nt*8 + (lane&3)*2;
                #pragma unroll
                for(int i=0;i<4;i++){
                    int pl = pl0 + (i>>1)*8;
                    int co = co0 + (i&1);
                    if(co < 73) stage[pl*76 + co] = acc[mt][nt][i];
                }
            }
        }
        __syncthreads();
        const int pix = tid >> 1, half = tid & 1;
        const int pe = pbase + pix;
        if(pe < NPIX){
            if(half == 0) g_rw[(long)b*NP + pe] = stage[pix*76 + 72];
            const float* row = stage + pix*76;
            #pragma unroll
            for(int a = half*4; a < half*4+4; a++){
                float t9[9];
                #pragma unroll
                for(int k=0;k<9;k++) t9[k] = row[a*9 + k];
                float m = t9[0];
                #pragma unroll
                for(int k=1;k<9;k++) m = fmaxf(m, t9[k]);
                float s = 0.f;
                #pragma unroll
                for(int k=0;k<9;k++){ t9[k] = __expf(t9[k]-m); s += t9[k]; }
                float inv = 1.f/s;
                #pragma unroll
                for(int k=0;k<9;k++)
                    g_tr[((long)b*72 + a*9 + k)*NP + pe] = t9[k]*inv;
            }
        }
    }
}

// ============================================================================
// Value iteration: K=30 steps, block per batch, v ping-pong in smem
// ============================================================================
__global__ void vi_kernel(){
    __shared__ float vp[2][53*53];
    __shared__ float rw[NP];
    const int b = blockIdx.x, tid = threadIdx.x;
    for(int i=tid;i<2*53*53;i+=blockDim.x) ((float*)vp)[i]=0.f;
    for(int i=tid;i<NP;i+=blockDim.x) rw[i]=g_rw[(long)b*NP + i];
    __syncthreads();

    const float* sTb = g_tr + (long)b*72*NP;
    for(int t=0;t<KK;t++){
        const int cur = t&1, nxt = cur^1;
        const bool last = (t==KK-1);
        for(int p=tid;p<NP;p+=blockDim.x){
            int y=p/HP, x=p%HP;
            float n[9];
            #pragma unroll
            for(int i=0;i<3;i++)
                #pragma unroll
                for(int j=0;j<3;j++)
                    n[i*3+j] = vp[cur][(y+i)*53 + (x+j)];
            float r = rw[p];
            float vmax = -3.4e38f;
            #pragma unroll 2
            for(int a=0;a<AA;a++){
                const float* s = sTb + a*9*NP + p;
                float q0 = fmaf(s[0*NP], n[0], r);
                q0 = fmaf(s[3*NP], n[3], q0);
                q0 = fmaf(s[6*NP], n[6], q0);
                float q1 = s[1*NP]*n[1];
                q1 = fmaf(s[4*NP], n[4], q1);
                q1 = fmaf(s[7*NP], n[7], q1);
                float q2 = s[2*NP]*n[2];
                q2 = fmaf(s[5*NP], n[5], q2);
                q2 = fmaf(s[8*NP], n[8], q2);
                float q = q0+q1+q2;
                if(last) g_q[((long)b*AA+a)*NP + p] = q;
                vmax = fmaxf(vmax, q);
            }
            vp[nxt][(y+1)*53 + (x+1)] = vmax;
        }
        __syncthreads();
    }
}

// ============================================================================
// Head
// ============================================================================
__global__ void head_kernel(const float* __restrict__ a1w,
                            const float* __restrict__ a1b,
                            const float* __restrict__ a2w,
                            const float* __restrict__ a2b,
                            float* __restrict__ out){
    __shared__ float s1w[HIDD*AA], s1b[HIDD], s2w[AA*HIDD], s2b[AA];
    const int b = blockIdx.x, tid = threadIdx.x;
    for(int i=tid;i<HIDD*AA;i+=blockDim.x){ s1w[i]=a1w[i]; s2w[i]=a2w[i]; }
    for(int i=tid;i<HIDD;i+=blockDim.x) s1b[i]=a1b[i];
    if(tid<AA) s2b[tid]=a2b[tid];
    __syncthreads();

    for(int p=tid;p<GG;p+=blockDim.x){
        int y=p/G, x=p%G;
        float q[AA], l[AA];
        #pragma unroll
        for(int a=0;a<AA;a++) q[a] = g_q[((long)b*AA+a)*NP + y*HP + x];
        #pragma unroll
        for(int a=0;a<AA;a++) l[a] = s2b[a];
        for(int c=0;c<HIDD;c++){
            float m = s1b[c];
            #pragma unroll
            for(int a=0;a<AA;a++) m = fmaf(q[a], s1w[c*AA+a], m);
            m = fmaxf(m, 0.f);
            #pragma unroll
            for(int a=0;a<AA;a++) l[a] = fmaf(m, s2w[a*HIDD+c], l[a]);
        }
        #pragma unroll
        for(int a=0;a<AA;a++) out[(((long)b*AA+a)*G+y)*G + x] = l[a];
    }
}

__global__ void dummy_kernel(){}

// ============================================================================
extern "C" void kernel_launch(void* const* d_in, const int* in_sizes, int n_in,
                              void* d_out, int out_size){
    const float* gin = (const float*)d_in[0];
    const float* h1w = (const float*)d_in[3];
    const float* h1b = (const float*)d_in[4];
    const float* h2w = (const float*)d_in[5];
    const float* h2b = (const float*)d_in[6];
    const float* rww = (const float*)d_in[7];
    const float* tww = (const float*)d_in[8];
    const float* a1w = (const float*)d_in[9];
    const float* a1b = (const float*)d_in[10];
    const float* a2w = (const float*)d_in[11];
    const float* a2b = (const float*)d_in[12];
    float* out = (float*)d_out;

    __nv_bfloat16 *h1h, *h1l, *h2h, *h2l, *w2h, *w2l, *wth, *wtl;
    cudaGetSymbolAddress((void**)&h1h, g_h1h);
    cudaGetSymbolAddress((void**)&h1l, g_h1l);
    cudaGetSymbolAddress((void**)&h2h, g_h2h);
    cudaGetSymbolAddress((void**)&h2l, g_h2l);
    cudaGetSymbolAddress((void**)&w2h, g_w2h);
    cudaGetSymbolAddress((void**)&w2l, g_w2l);
    cudaGetSymbolAddress((void**)&wth, g_wth);
    cudaGetSymbolAddress((void**)&wtl, g_wtl);

    auto conv2a_k = conv_shift_kernel<G, GG, P1W, P1N, 192, 96, false>;
    auto conv2b_k = conv_shift_kernel<G, GG, P1W, P1N, 192, 64, false>;
    auto trans_k  = conv_shift_kernel<HP, NP, P2W, P2N, 128, 96, true>;
    const int ASZ = 256*48;
    const int smem96 = 4*ASZ + 2*(3*2*96*48);   // 104448
    const int smem64 = 4*ASZ + 2*(3*2*64*48);   // 86016
    cudaFuncSetAttribute(conv2a_k, cudaFuncAttributeMaxDynamicSharedMemorySize, smem96);
    cudaFuncSetAttribute(conv2b_k, cudaFuncAttributeMaxDynamicSharedMemorySize, smem64);
    cudaFuncSetAttribute(trans_k,  cudaFuncAttributeMaxDynamicSharedMemorySize, smem96);

    {
        int n = 9*NCH*192*16 + 9*NCH*128*16;
        prep_w_kernel<<<(n+255)/256, 256>>>(h2w, tww, rww);
    }
    conv1_kernel<<<dim3(5,1,BB), 256>>>(gin, h1w, h1b);
    dummy_kernel<<<1, 32>>>();
    conv2a_k<<<dim3(19, BB), 256, smem96>>>(h1h, h1l, w2h, w2l, h2b, 0,  h2h, h2l);
    conv2b_k<<<dim3(19, BB), 256, smem64>>>(h1h, h1l, w2h, w2l, h2b, 96, h2h, h2l);
    trans_k <<<dim3(21, BB), 256, smem96>>>(h2h, h2l, wth, wtl, nullptr, 0, nullptr, nullptr);
    vi_kernel<<<BB, 1024>>>();
    head_kernel<<<BB, 256>>>(a1w, a1b, a2w, a2b, out);
}